// round 1
// baseline (speedup 1.0000x reference)
#include <cuda_runtime.h>
#include <cuda_bf16.h>

// Problem constants (shapes fixed by the dataset)
#define N_NODES   50000
#define N_FILTERS 4096
#define EDGE_FEAT 32
#define HIDDEN    128
#define IN_CH     16
#define OUT_CH    16

// Scratch: dynamic per-filter weight matrices [F, 16, 16] and segment offsets.
__device__ float g_weights[N_FILTERS * IN_CH * OUT_CH];   // 4 MB
__device__ int   g_segstart[N_NODES + 1];

// ---------------------------------------------------------------------------
// Kernel 1: filter net.  weights[f] = relu(ef[f] @ W1 + b1) @ W2 + b2
// One block handles FPB filters. 256 threads.
// ---------------------------------------------------------------------------
#define FPB 32
__global__ void filter_net_kernel(const float* __restrict__ ef,
                                  const float* __restrict__ W1,
                                  const float* __restrict__ b1,
                                  const float* __restrict__ W2,
                                  const float* __restrict__ b2) {
    __shared__ float s_ef[FPB * EDGE_FEAT];     // 4 KB
    __shared__ float s_h[HIDDEN * FPB];         // h transposed [k][f], 16 KB

    const int t  = threadIdx.x;                 // 0..255
    const int f0 = blockIdx.x * FPB;

    // Load edge features for this block's filters
    for (int idx = t; idx < FPB * EDGE_FEAT; idx += 256) {
        int f = idx / EDGE_FEAT, j = idx % EDGE_FEAT;
        s_ef[f * EDGE_FEAT + j] = ef[(f0 + f) * EDGE_FEAT + j];
    }
    __syncthreads();

    // Phase 1: h[f][k] = relu(b1[k] + sum_j ef[f][j] * W1[j][k])
    // thread -> k = t & 127, filter half fg = t >> 7 (16 filters each)
    {
        const int k  = t & 127;
        const int fg = t >> 7;
        float accs[16];
        const float bb = b1[k];
#pragma unroll
        for (int f = 0; f < 16; f++) accs[f] = bb;
        for (int j = 0; j < EDGE_FEAT; j++) {
            const float w1 = W1[j * HIDDEN + k];
#pragma unroll
            for (int f = 0; f < 16; f++)
                accs[f] = fmaf(s_ef[(fg * 16 + f) * EDGE_FEAT + j], w1, accs[f]);
        }
#pragma unroll
        for (int f = 0; f < 16; f++)
            s_h[k * FPB + fg * 16 + f] = fmaxf(accs[f], 0.0f);
    }
    __syncthreads();

    // Phase 2: weights[f][m] = b2[m] + sum_k h[f][k] * W2[k][m], m = t (0..255)
    {
        float acc2[FPB];
        const float bb2 = b2[t];
#pragma unroll
        for (int f = 0; f < FPB; f++) acc2[f] = bb2;
        for (int kk = 0; kk < HIDDEN; kk++) {
            const float w2 = W2[kk * 256 + t];
#pragma unroll
            for (int f = 0; f < FPB; f++)
                acc2[f] = fmaf(s_h[kk * FPB + f], w2, acc2[f]);
        }
#pragma unroll
        for (int f = 0; f < FPB; f++)
            g_weights[(f0 + f) * 256 + t] = acc2[f];
    }
}

// ---------------------------------------------------------------------------
// Kernel 2: per-node segment offsets via binary search on sorted seg_ids.
// g_segstart[n] = first edge index e with seg_ids[e] >= n.
// ---------------------------------------------------------------------------
__global__ void seg_offsets_kernel(const int* __restrict__ seg_ids, int nE, int nNodes) {
    int n = blockIdx.x * blockDim.x + threadIdx.x;
    if (n > nNodes) return;
    int lo = 0, hi = nE;
    while (lo < hi) {
        int mid = (lo + hi) >> 1;
        if (__ldg(&seg_ids[mid]) < n) lo = mid + 1; else hi = mid;
    }
    g_segstart[n] = lo;
}

// ---------------------------------------------------------------------------
// Kernel 3: fused edge bmm + segment mean.
// One warp per node; two edges in flight (one per half-warp); lane = out ch.
// ---------------------------------------------------------------------------
#define WARPS_PER_BLOCK 8
__global__ void edge_conv_kernel(const float* __restrict__ input,
                                 const int*   __restrict__ idxn,
                                 const int*   __restrict__ idxe,
                                 float*       __restrict__ out,
                                 int nNodes) {
    const int warp_id = (blockIdx.x * WARPS_PER_BLOCK) + (threadIdx.x >> 5);
    if (warp_id >= nNodes) return;
    const int node = warp_id;

    const int lane = threadIdx.x & 31;
    const int half = lane >> 4;      // which edge of the pair
    const int o    = lane & 15;      // output channel

    const int beg = g_segstart[node];
    const int end = g_segstart[node + 1];
    const int deg = end - beg;

    float acc = 0.0f;
    const int nPairs = (deg + 1) >> 1;

    for (int p = 0; p < nPairs; ++p) {
        const int e      = beg + 2 * p + half;
        const bool valid = (e < end);
        const int ee     = valid ? e : beg;          // beg < end here (nPairs>0)
        const int nIdx   = __ldg(&idxn[ee]);
        const int f      = __ldg(&idxe[ee]);
        const float xo   = valid ? __ldg(&input[nIdx * IN_CH + o]) : 0.0f;
        const float* wrow = g_weights + f * 256;
#pragma unroll
        for (int i = 0; i < 16; i++) {
            // broadcast x_i within this half-warp
            const float xi = __shfl_sync(0xffffffffu, xo, i, 16);
            const float wv = valid ? __ldg(&wrow[i * 16 + o]) : 0.0f;
            acc = fmaf(xi, wv, acc);
        }
    }

    // combine the two half-warp accumulators
    acc += __shfl_xor_sync(0xffffffffu, acc, 16);

    if (lane < 16) {
        out[node * OUT_CH + o] = (deg > 0) ? (acc / (float)deg) : 0.0f;
    }
}

// ---------------------------------------------------------------------------
// Launch
// Inputs (metadata order): input, idxn, idxe, seg_ids, edgefeats, W1, b1, W2, b2
// ---------------------------------------------------------------------------
extern "C" void kernel_launch(void* const* d_in, const int* in_sizes, int n_in,
                              void* d_out, int out_size) {
    const float* input = (const float*)d_in[0];
    const int*   idxn  = (const int*)  d_in[1];
    const int*   idxe  = (const int*)  d_in[2];
    const int*   segs  = (const int*)  d_in[3];
    const float* ef    = (const float*)d_in[4];
    const float* W1    = (const float*)d_in[5];
    const float* b1    = (const float*)d_in[6];
    const float* W2    = (const float*)d_in[7];
    const float* b2    = (const float*)d_in[8];
    float* out = (float*)d_out;

    const int nNodes  = in_sizes[0] / IN_CH;
    const int nEdges  = in_sizes[1];
    const int nFilt   = in_sizes[4] / EDGE_FEAT;

    // K1: filter net -> g_weights
    filter_net_kernel<<<nFilt / FPB, 256>>>(ef, W1, b1, W2, b2);

    // K2: segment offsets (nNodes+1 entries)
    {
        int threads = 256;
        int blocks = (nNodes + 1 + threads - 1) / threads;
        seg_offsets_kernel<<<blocks, threads>>>(segs, nEdges, nNodes);
    }

    // K3: fused edge bmm + segment mean
    {
        int blocks = (nNodes + WARPS_PER_BLOCK - 1) / WARPS_PER_BLOCK;
        edge_conv_kernel<<<blocks, WARPS_PER_BLOCK * 32>>>(input, idxn, idxe, out, nNodes);
    }
}

// round 2
// speedup vs baseline: 1.0436x; 1.0436x over previous
#include <cuda_runtime.h>
#include <cuda_bf16.h>

#define N_NODES   50000
#define N_FILTERS 4096
#define EDGE_FEAT 32
#define HIDDEN    128
#define IN_CH     16
#define OUT_CH    16
#define MAX_EDGES 1600000

// ---- scratch (static device globals; no dynamic allocation) ----
__device__ float g_weights[N_FILTERS * IN_CH * OUT_CH];   // 4 MB
__device__ int   g_segstart[N_NODES + 1];
__device__ int   g_hist[N_FILTERS];
__device__ int   g_offs[N_FILTERS + 1];
__device__ int   g_cursor[N_FILTERS];
__device__ int2  g_sorted[MAX_EDGES];                     // {orig edge id, src node}
__device__ float g_products[(size_t)MAX_EDGES * OUT_CH];  // 102 MB

// ---------------------------------------------------------------------------
// K1: filter net.  weights[f] = relu(ef[f] @ W1 + b1) @ W2 + b2
// FPB=8 filters per block -> 512 blocks (good wave coverage on 148 SMs).
// ---------------------------------------------------------------------------
#define FPB 8
__global__ void filter_net_kernel(const float* __restrict__ ef,
                                  const float* __restrict__ W1,
                                  const float* __restrict__ b1,
                                  const float* __restrict__ W2,
                                  const float* __restrict__ b2) {
    __shared__ float s_ef[FPB * EDGE_FEAT];   // 1 KB
    __shared__ float s_h[HIDDEN * FPB];       // [k][f], 4 KB

    const int t  = threadIdx.x;               // 0..255
    const int f0 = blockIdx.x * FPB;

    if (t < FPB * EDGE_FEAT)
        s_ef[t] = ef[f0 * EDGE_FEAT + t];
    __syncthreads();

    // Phase 1: h[f][k] = relu(b1[k] + sum_j ef[f][j]*W1[j][k])
    {
        const int k  = t & 127;
        const int fg = (t >> 7) * 4;          // 4 filters per thread
        float accs[4];
        const float bb = b1[k];
#pragma unroll
        for (int f = 0; f < 4; f++) accs[f] = bb;
        for (int j = 0; j < EDGE_FEAT; j++) {
            const float w1 = W1[j * HIDDEN + k];
#pragma unroll
            for (int f = 0; f < 4; f++)
                accs[f] = fmaf(s_ef[(fg + f) * EDGE_FEAT + j], w1, accs[f]);
        }
#pragma unroll
        for (int f = 0; f < 4; f++)
            s_h[k * FPB + fg + f] = fmaxf(accs[f], 0.0f);
    }
    __syncthreads();

    // Phase 2: weights[f][m] = b2[m] + sum_k h[f][k]*W2[k][m], m = t
    {
        float acc2[FPB];
        const float bb2 = b2[t];
#pragma unroll
        for (int f = 0; f < FPB; f++) acc2[f] = bb2;
        for (int kk = 0; kk < HIDDEN; kk++) {
            const float w2 = W2[kk * 256 + t];
#pragma unroll
            for (int f = 0; f < FPB; f++)
                acc2[f] = fmaf(s_h[kk * FPB + f], w2, acc2[f]);
        }
#pragma unroll
        for (int f = 0; f < FPB; f++)
            g_weights[(f0 + f) * 256 + t] = acc2[f];
    }
}

// ---------------------------------------------------------------------------
// K2: per-node segment offsets via binary search on sorted seg_ids.
// ---------------------------------------------------------------------------
__global__ void seg_offsets_kernel(const int* __restrict__ seg_ids, int nE, int nNodes) {
    int n = blockIdx.x * blockDim.x + threadIdx.x;
    if (n > nNodes) return;
    int lo = 0, hi = nE;
    while (lo < hi) {
        int mid = (lo + hi) >> 1;
        if (__ldg(&seg_ids[mid]) < n) lo = mid + 1; else hi = mid;
    }
    g_segstart[n] = lo;
}

// ---------------------------------------------------------------------------
// K3a: zero filter histogram
// ---------------------------------------------------------------------------
__global__ void zero_hist_kernel() {
    int i = blockIdx.x * blockDim.x + threadIdx.x;
    if (i < N_FILTERS) g_hist[i] = 0;
}

// ---------------------------------------------------------------------------
// K3b: histogram of idxe with smem privatization
// ---------------------------------------------------------------------------
#define HIST_BLOCKS 128
#define HIST_THREADS 512
__global__ void hist_kernel(const int* __restrict__ idxe, int nE) {
    __shared__ int sh[N_FILTERS];   // 16 KB
    const int t = threadIdx.x;
    for (int i = t; i < N_FILTERS; i += HIST_THREADS) sh[i] = 0;
    __syncthreads();
    for (int e = blockIdx.x * HIST_THREADS + t; e < nE; e += HIST_BLOCKS * HIST_THREADS)
        atomicAdd(&sh[__ldg(&idxe[e])], 1);
    __syncthreads();
    for (int i = t; i < N_FILTERS; i += HIST_THREADS) {
        int c = sh[i];
        if (c) atomicAdd(&g_hist[i], c);
    }
}

// ---------------------------------------------------------------------------
// K4: exclusive scan over 4096 counts, single block of 1024 threads.
// ---------------------------------------------------------------------------
__global__ void scan_kernel() {
    __shared__ int s_part[1024];
    const int t = threadIdx.x;
    const int base = t * 4;
    int c0 = g_hist[base], c1 = g_hist[base + 1], c2 = g_hist[base + 2], c3 = g_hist[base + 3];
    int sum = c0 + c1 + c2 + c3;
    s_part[t] = sum;
    __syncthreads();
    for (int off = 1; off < 1024; off <<= 1) {
        int v = (t >= off) ? s_part[t - off] : 0;
        __syncthreads();
        s_part[t] += v;
        __syncthreads();
    }
    int excl = s_part[t] - sum;
    g_offs[base]     = excl;
    g_offs[base + 1] = excl + c0;
    g_offs[base + 2] = excl + c0 + c1;
    g_offs[base + 3] = excl + c0 + c1 + c2;
    g_cursor[base]     = excl;
    g_cursor[base + 1] = excl + c0;
    g_cursor[base + 2] = excl + c0 + c1;
    g_cursor[base + 3] = excl + c0 + c1 + c2;
    if (t == 1023) g_offs[N_FILTERS] = s_part[1023];
}

// ---------------------------------------------------------------------------
// K5: scatter edges into filter-sorted order (stores {orig_e, src_node})
// ---------------------------------------------------------------------------
__global__ void scatter_kernel(const int* __restrict__ idxn,
                               const int* __restrict__ idxe, int nE) {
    for (int e = blockIdx.x * blockDim.x + threadIdx.x; e < nE;
         e += gridDim.x * blockDim.x) {
        int f = __ldg(&idxe[e]);
        int pos = atomicAdd(&g_cursor[f], 1);
        g_sorted[pos] = make_int2(e, __ldg(&idxn[e]));
    }
}

// ---------------------------------------------------------------------------
// K6: per-filter products. One block per filter; weights in smem (broadcast).
// products[orig_e][o] = sum_i x[n][i] * w[i][o]
// ---------------------------------------------------------------------------
#define PT 128
__global__ void product_kernel(const float* __restrict__ input) {
    const int f = blockIdx.x;
    __shared__ float ws[256];
    const int t = threadIdx.x;
    ws[t]       = g_weights[f * 256 + t];
    ws[t + 128] = g_weights[f * 256 + 128 + t];
    const int beg = g_offs[f], end = g_offs[f + 1];
    __syncthreads();

    const float4* __restrict__ w4 = (const float4*)ws;

    for (int p = beg + t; p < end; p += PT) {
        int2 se = g_sorted[p];
        const int e = se.x, n = se.y;
        const float4* xp = (const float4*)(input + (size_t)n * IN_CH);
        float4 x0 = __ldg(&xp[0]), x1 = __ldg(&xp[1]);
        float4 x2 = __ldg(&xp[2]), x3 = __ldg(&xp[3]);
        float xr[16] = {x0.x, x0.y, x0.z, x0.w,  x1.x, x1.y, x1.z, x1.w,
                        x2.x, x2.y, x2.z, x2.w,  x3.x, x3.y, x3.z, x3.w};
        float4 a0 = make_float4(0.f, 0.f, 0.f, 0.f);
        float4 a1 = a0, a2 = a0, a3 = a0;
#pragma unroll
        for (int i = 0; i < 16; i++) {
            const float xi = xr[i];
            float4 w;
            w = w4[i * 4 + 0];
            a0.x = fmaf(xi, w.x, a0.x); a0.y = fmaf(xi, w.y, a0.y);
            a0.z = fmaf(xi, w.z, a0.z); a0.w = fmaf(xi, w.w, a0.w);
            w = w4[i * 4 + 1];
            a1.x = fmaf(xi, w.x, a1.x); a1.y = fmaf(xi, w.y, a1.y);
            a1.z = fmaf(xi, w.z, a1.z); a1.w = fmaf(xi, w.w, a1.w);
            w = w4[i * 4 + 2];
            a2.x = fmaf(xi, w.x, a2.x); a2.y = fmaf(xi, w.y, a2.y);
            a2.z = fmaf(xi, w.z, a2.z); a2.w = fmaf(xi, w.w, a2.w);
            w = w4[i * 4 + 3];
            a3.x = fmaf(xi, w.x, a3.x); a3.y = fmaf(xi, w.y, a3.y);
            a3.z = fmaf(xi, w.z, a3.z); a3.w = fmaf(xi, w.w, a3.w);
        }
        float4* op = (float4*)(g_products + (size_t)e * OUT_CH);
        op[0] = a0; op[1] = a1; op[2] = a2; op[3] = a3;
    }
}

// ---------------------------------------------------------------------------
// K7: segment mean over products (original edge order -> sequential reads).
// One warp per node; half-warp per edge; lane = out channel.
// ---------------------------------------------------------------------------
#define WARPS_PER_BLOCK 8
__global__ void seg_mean_kernel(float* __restrict__ out, int nNodes) {
    const int warp_id = blockIdx.x * WARPS_PER_BLOCK + (threadIdx.x >> 5);
    if (warp_id >= nNodes) return;

    const int lane = threadIdx.x & 31;
    const int half = lane >> 4;
    const int o    = lane & 15;

    const int beg = g_segstart[warp_id];
    const int end = g_segstart[warp_id + 1];
    const int deg = end - beg;

    float acc = 0.0f;
    for (int e = beg + half; e < end; e += 2)
        acc += g_products[(size_t)e * OUT_CH + o];

    acc += __shfl_xor_sync(0xffffffffu, acc, 16);
    if (lane < 16)
        out[warp_id * OUT_CH + o] = (deg > 0) ? (acc / (float)deg) : 0.0f;
}

// ---------------------------------------------------------------------------
// Launch.  Inputs: input, idxn, idxe, seg_ids, edgefeats, W1, b1, W2, b2
// ---------------------------------------------------------------------------
extern "C" void kernel_launch(void* const* d_in, const int* in_sizes, int n_in,
                              void* d_out, int out_size) {
    const float* input = (const float*)d_in[0];
    const int*   idxn  = (const int*)  d_in[1];
    const int*   idxe  = (const int*)  d_in[2];
    const int*   segs  = (const int*)  d_in[3];
    const float* ef    = (const float*)d_in[4];
    const float* W1    = (const float*)d_in[5];
    const float* b1    = (const float*)d_in[6];
    const float* W2    = (const float*)d_in[7];
    const float* b2    = (const float*)d_in[8];
    float* out = (float*)d_out;

    const int nNodes = in_sizes[0] / IN_CH;
    const int nEdges = in_sizes[1];
    const int nFilt  = in_sizes[4] / EDGE_FEAT;

    filter_net_kernel<<<nFilt / FPB, 256>>>(ef, W1, b1, W2, b2);

    {
        int threads = 256;
        int blocks = (nNodes + 1 + threads - 1) / threads;
        seg_offsets_kernel<<<blocks, threads>>>(segs, nEdges, nNodes);
    }

    zero_hist_kernel<<<(N_FILTERS + 255) / 256, 256>>>();
    hist_kernel<<<HIST_BLOCKS, HIST_THREADS>>>(idxe, nEdges);
    scan_kernel<<<1, 1024>>>();
    scatter_kernel<<<512, 256>>>(idxn, idxe, nEdges);

    product_kernel<<<nFilt, PT>>>(input);

    {
        int blocks = (nNodes + WARPS_PER_BLOCK - 1) / WARPS_PER_BLOCK;
        seg_mean_kernel<<<blocks, WARPS_PER_BLOCK * 32>>>(out, nNodes);
    }
}

// round 3
// speedup vs baseline: 1.1745x; 1.1254x over previous
#include <cuda_runtime.h>
#include <cuda_fp16.h>

#define N_NODES   50000
#define N_FILTERS 4096
#define EDGE_FEAT 32
#define HIDDEN    128
#define IN_CH     16
#define OUT_CH    16
#define MAX_EDGES 1600000

// ---- scratch (static device globals; no dynamic allocation) ----
__device__ float  g_weights[N_FILTERS * IN_CH * OUT_CH];   // 4 MB
__device__ int    g_segstart[N_NODES + 1];
__device__ int    g_hist[N_FILTERS];
__device__ int    g_offs[N_FILTERS + 1];
__device__ int    g_cursor[N_FILTERS];
__device__ int2   g_sorted[MAX_EDGES];                     // {orig edge id, src node}
__device__ __half g_products[(size_t)MAX_EDGES * OUT_CH];  // 51 MB (fp16)

// ---------------------------------------------------------------------------
// K1: filter net.  weights[f] = relu(ef[f] @ W1 + b1) @ W2 + b2
// ---------------------------------------------------------------------------
#define FPB 8
__global__ void filter_net_kernel(const float* __restrict__ ef,
                                  const float* __restrict__ W1,
                                  const float* __restrict__ b1,
                                  const float* __restrict__ W2,
                                  const float* __restrict__ b2) {
    __shared__ float s_ef[FPB * EDGE_FEAT];   // 1 KB
    __shared__ float s_h[HIDDEN * FPB];       // [k][f], 4 KB

    const int t  = threadIdx.x;               // 0..255
    const int f0 = blockIdx.x * FPB;

    if (t < FPB * EDGE_FEAT)
        s_ef[t] = ef[f0 * EDGE_FEAT + t];
    __syncthreads();

    {
        const int k  = t & 127;
        const int fg = (t >> 7) * 4;          // 4 filters per thread
        float accs[4];
        const float bb = b1[k];
#pragma unroll
        for (int f = 0; f < 4; f++) accs[f] = bb;
        for (int j = 0; j < EDGE_FEAT; j++) {
            const float w1 = W1[j * HIDDEN + k];
#pragma unroll
            for (int f = 0; f < 4; f++)
                accs[f] = fmaf(s_ef[(fg + f) * EDGE_FEAT + j], w1, accs[f]);
        }
#pragma unroll
        for (int f = 0; f < 4; f++)
            s_h[k * FPB + fg + f] = fmaxf(accs[f], 0.0f);
    }
    __syncthreads();

    {
        float acc2[FPB];
        const float bb2 = b2[t];
#pragma unroll
        for (int f = 0; f < FPB; f++) acc2[f] = bb2;
        for (int kk = 0; kk < HIDDEN; kk++) {
            const float w2 = W2[kk * 256 + t];
#pragma unroll
            for (int f = 0; f < FPB; f++)
                acc2[f] = fmaf(s_h[kk * FPB + f], w2, acc2[f]);
        }
#pragma unroll
        for (int f = 0; f < FPB; f++)
            g_weights[(f0 + f) * 256 + t] = acc2[f];
    }
}

// ---------------------------------------------------------------------------
// K2: per-node segment offsets (binary search) + zero the filter histogram.
// ---------------------------------------------------------------------------
__global__ void seg_offsets_kernel(const int* __restrict__ seg_ids, int nE, int nNodes) {
    int n = blockIdx.x * blockDim.x + threadIdx.x;
    if (n < N_FILTERS) g_hist[n] = 0;        // fused zeroing (grid covers 50001 > 4096)
    if (n > nNodes) return;
    int lo = 0, hi = nE;
    while (lo < hi) {
        int mid = (lo + hi) >> 1;
        if (__ldg(&seg_ids[mid]) < n) lo = mid + 1; else hi = mid;
    }
    g_segstart[n] = lo;
}

// ---------------------------------------------------------------------------
// K3: histogram of idxe, smem-privatized, vectorized, 2 blocks/SM.
// ---------------------------------------------------------------------------
#define HIST_BLOCKS 296
#define HIST_THREADS 512
__global__ void hist_kernel(const int* __restrict__ idxe, int nE) {
    __shared__ int sh[N_FILTERS];   // 16 KB
    const int t = threadIdx.x;
    for (int i = t; i < N_FILTERS; i += HIST_THREADS) sh[i] = 0;
    __syncthreads();
    const int nE4 = nE >> 2;
    const int4* __restrict__ idxe4 = (const int4*)idxe;
    for (int q = blockIdx.x * HIST_THREADS + t; q < nE4; q += HIST_BLOCKS * HIST_THREADS) {
        int4 v = __ldg(&idxe4[q]);
        atomicAdd(&sh[v.x], 1);
        atomicAdd(&sh[v.y], 1);
        atomicAdd(&sh[v.z], 1);
        atomicAdd(&sh[v.w], 1);
    }
    // tail
    if (blockIdx.x == 0) {
        for (int e = nE4 * 4 + t; e < nE; e += HIST_THREADS)
            atomicAdd(&sh[__ldg(&idxe[e])], 1);
    }
    __syncthreads();
    for (int i = t; i < N_FILTERS; i += HIST_THREADS) {
        int c = sh[i];
        if (c) atomicAdd(&g_hist[i], c);
    }
}

// ---------------------------------------------------------------------------
// K4: exclusive scan over 4096 counts, single block of 1024 threads.
// ---------------------------------------------------------------------------
__global__ void scan_kernel() {
    __shared__ int s_part[1024];
    const int t = threadIdx.x;
    const int base = t * 4;
    int c0 = g_hist[base], c1 = g_hist[base + 1], c2 = g_hist[base + 2], c3 = g_hist[base + 3];
    int sum = c0 + c1 + c2 + c3;
    s_part[t] = sum;
    __syncthreads();
    for (int off = 1; off < 1024; off <<= 1) {
        int v = (t >= off) ? s_part[t - off] : 0;
        __syncthreads();
        s_part[t] += v;
        __syncthreads();
    }
    int excl = s_part[t] - sum;
    g_offs[base]     = excl;
    g_offs[base + 1] = excl + c0;
    g_offs[base + 2] = excl + c0 + c1;
    g_offs[base + 3] = excl + c0 + c1 + c2;
    g_cursor[base]     = excl;
    g_cursor[base + 1] = excl + c0;
    g_cursor[base + 2] = excl + c0 + c1;
    g_cursor[base + 3] = excl + c0 + c1 + c2;
    if (t == 1023) g_offs[N_FILTERS] = s_part[1023];
}

// ---------------------------------------------------------------------------
// K5: scatter edges into filter-sorted order, 4 edges per thread.
// ---------------------------------------------------------------------------
__global__ void scatter_kernel(const int* __restrict__ idxn,
                               const int* __restrict__ idxe, int nE) {
    const int nE4 = nE >> 2;
    const int4* __restrict__ idxe4 = (const int4*)idxe;
    const int4* __restrict__ idxn4 = (const int4*)idxn;
    for (int q = blockIdx.x * blockDim.x + threadIdx.x; q < nE4;
         q += gridDim.x * blockDim.x) {
        int4 f = __ldg(&idxe4[q]);
        int4 n = __ldg(&idxn4[q]);
        int e = q * 4;
        g_sorted[atomicAdd(&g_cursor[f.x], 1)] = make_int2(e,     n.x);
        g_sorted[atomicAdd(&g_cursor[f.y], 1)] = make_int2(e + 1, n.y);
        g_sorted[atomicAdd(&g_cursor[f.z], 1)] = make_int2(e + 2, n.z);
        g_sorted[atomicAdd(&g_cursor[f.w], 1)] = make_int2(e + 3, n.w);
    }
    // tail
    if (blockIdx.x == 0) {
        for (int e = nE4 * 4 + threadIdx.x; e < nE; e += blockDim.x) {
            int f = __ldg(&idxe[e]);
            g_sorted[atomicAdd(&g_cursor[f], 1)] = make_int2(e, __ldg(&idxn[e]));
        }
    }
}

// ---------------------------------------------------------------------------
// K6: per-filter products -> fp16. One block per filter; weights in smem.
// ---------------------------------------------------------------------------
#define PT 128
__global__ void product_kernel(const float* __restrict__ input) {
    const int f = blockIdx.x;
    __shared__ float ws[256];
    const int t = threadIdx.x;
    ws[t]       = g_weights[f * 256 + t];
    ws[t + 128] = g_weights[f * 256 + 128 + t];
    const int beg = g_offs[f], end = g_offs[f + 1];
    __syncthreads();

    const float4* __restrict__ w4 = (const float4*)ws;

    for (int p = beg + t; p < end; p += PT) {
        int2 se = g_sorted[p];
        const int e = se.x, n = se.y;
        const float4* xp = (const float4*)(input + (size_t)n * IN_CH);
        float4 x0 = __ldg(&xp[0]), x1 = __ldg(&xp[1]);
        float4 x2 = __ldg(&xp[2]), x3 = __ldg(&xp[3]);
        float xr[16] = {x0.x, x0.y, x0.z, x0.w,  x1.x, x1.y, x1.z, x1.w,
                        x2.x, x2.y, x2.z, x2.w,  x3.x, x3.y, x3.z, x3.w};
        float4 a0 = make_float4(0.f, 0.f, 0.f, 0.f);
        float4 a1 = a0, a2 = a0, a3 = a0;
#pragma unroll
        for (int i = 0; i < 16; i++) {
            const float xi = xr[i];
            float4 w;
            w = w4[i * 4 + 0];
            a0.x = fmaf(xi, w.x, a0.x); a0.y = fmaf(xi, w.y, a0.y);
            a0.z = fmaf(xi, w.z, a0.z); a0.w = fmaf(xi, w.w, a0.w);
            w = w4[i * 4 + 1];
            a1.x = fmaf(xi, w.x, a1.x); a1.y = fmaf(xi, w.y, a1.y);
            a1.z = fmaf(xi, w.z, a1.z); a1.w = fmaf(xi, w.w, a1.w);
            w = w4[i * 4 + 2];
            a2.x = fmaf(xi, w.x, a2.x); a2.y = fmaf(xi, w.y, a2.y);
            a2.z = fmaf(xi, w.z, a2.z); a2.w = fmaf(xi, w.w, a2.w);
            w = w4[i * 4 + 3];
            a3.x = fmaf(xi, w.x, a3.x); a3.y = fmaf(xi, w.y, a3.y);
            a3.z = fmaf(xi, w.z, a3.z); a3.w = fmaf(xi, w.w, a3.w);
        }
        // pack 16 floats -> 16 halfs (32 B) -> two 16B stores
        __half2 h[8];
        h[0] = __floats2half2_rn(a0.x, a0.y); h[1] = __floats2half2_rn(a0.z, a0.w);
        h[2] = __floats2half2_rn(a1.x, a1.y); h[3] = __floats2half2_rn(a1.z, a1.w);
        h[4] = __floats2half2_rn(a2.x, a2.y); h[5] = __floats2half2_rn(a2.z, a2.w);
        h[6] = __floats2half2_rn(a3.x, a3.y); h[7] = __floats2half2_rn(a3.z, a3.w);
        uint4* op = (uint4*)(g_products + (size_t)e * OUT_CH);
        op[0] = *(uint4*)&h[0];
        op[1] = *(uint4*)&h[4];
    }
}

// ---------------------------------------------------------------------------
// K7: segment mean over fp16 products. One warp per node; 4 edges in flight
// (8 lanes per edge, each lane owns a half2 = 2 output channels).
// ---------------------------------------------------------------------------
#define WARPS_PER_BLOCK 8
__global__ void seg_mean_kernel(float* __restrict__ out, int nNodes) {
    const int warp_id = blockIdx.x * WARPS_PER_BLOCK + (threadIdx.x >> 5);
    if (warp_id >= nNodes) return;

    const int lane = threadIdx.x & 31;
    const int g = lane >> 3;      // edge slot 0..3
    const int c = lane & 7;       // half2 index -> channels 2c, 2c+1

    const int beg = g_segstart[warp_id];
    const int end = g_segstart[warp_id + 1];
    const int deg = end - beg;

    const __half2* __restrict__ prod2 = (const __half2*)g_products;

    float ax = 0.0f, ay = 0.0f;
    for (int e = beg + g; e < end; e += 4) {
        float2 v = __half22float2(__ldg(&prod2[(size_t)e * 8 + c]));
        ax += v.x; ay += v.y;
    }

    // reduce across the 4 edge slots (lanes differing in bits 3,4)
    ax += __shfl_xor_sync(0xffffffffu, ax, 8);
    ay += __shfl_xor_sync(0xffffffffu, ay, 8);
    ax += __shfl_xor_sync(0xffffffffu, ax, 16);
    ay += __shfl_xor_sync(0xffffffffu, ay, 16);

    if (lane < 8) {
        float inv = (deg > 0) ? (1.0f / (float)deg) : 0.0f;
        float2 r = make_float2(ax * inv, ay * inv);
        *(float2*)(out + (size_t)warp_id * OUT_CH + 2 * c) = r;
    }
}

// ---------------------------------------------------------------------------
// Launch.  Inputs: input, idxn, idxe, seg_ids, edgefeats, W1, b1, W2, b2
// ---------------------------------------------------------------------------
extern "C" void kernel_launch(void* const* d_in, const int* in_sizes, int n_in,
                              void* d_out, int out_size) {
    const float* input = (const float*)d_in[0];
    const int*   idxn  = (const int*)  d_in[1];
    const int*   idxe  = (const int*)  d_in[2];
    const int*   segs  = (const int*)  d_in[3];
    const float* ef    = (const float*)d_in[4];
    const float* W1    = (const float*)d_in[5];
    const float* b1    = (const float*)d_in[6];
    const float* W2    = (const float*)d_in[7];
    const float* b2    = (const float*)d_in[8];
    float* out = (float*)d_out;

    const int nNodes = in_sizes[0] / IN_CH;
    const int nEdges = in_sizes[1];
    const int nFilt  = in_sizes[4] / EDGE_FEAT;

    filter_net_kernel<<<nFilt / FPB, 256>>>(ef, W1, b1, W2, b2);

    {
        int threads = 256;
        int blocks = (nNodes + 1 + threads - 1) / threads;
        seg_offsets_kernel<<<blocks, threads>>>(segs, nEdges, nNodes);
    }

    hist_kernel<<<HIST_BLOCKS, HIST_THREADS>>>(idxe, nEdges);
    scan_kernel<<<1, 1024>>>();
    scatter_kernel<<<1024, 256>>>(idxn, idxe, nEdges);

    product_kernel<<<nFilt, PT>>>(input);

    {
        int blocks = (nNodes + WARPS_PER_BLOCK - 1) / WARPS_PER_BLOCK;
        seg_mean_kernel<<<blocks, WARPS_PER_BLOCK * 32>>>(out, nNodes);
    }
}

// round 4
// speedup vs baseline: 1.3491x; 1.1486x over previous
#include <cuda_runtime.h>
#include <cuda_fp16.h>

#define N_NODES   50000
#define N_FILTERS 4096
#define EDGE_FEAT 32
#define HIDDEN    128
#define IN_CH     16
#define OUT_CH    16
#define MAX_EDGES 1600000

// ---- scratch (static device globals; zero-initialized at module load) ----
__device__ float  g_weights[N_FILTERS * IN_CH * OUT_CH];   // 4 MB
__device__ int    g_segstart[N_NODES + 1];
__device__ int    g_hist[N_FILTERS];                       // self-cleaned by scan_kernel
__device__ int    g_offs[N_FILTERS + 1];
__device__ int    g_cursor[N_FILTERS];
__device__ int2   g_sorted[MAX_EDGES];                     // {orig edge id, src node}
__device__ __half g_products[(size_t)MAX_EDGES * OUT_CH];  // 51 MB (fp16)

typedef unsigned long long ull;

// packed f32x2 FMA: d = a*b + d  (two fp32 lanes per instruction)
__device__ __forceinline__ void fma2(ull& d, ull a, ull b) {
    asm("fma.rn.f32x2 %0, %1, %2, %0;" : "+l"(d) : "l"(a), "l"(b));
}
__device__ __forceinline__ ull pack2(float lo, float hi) {
    ull r;
    asm("mov.b64 %0, {%1, %2};" : "=l"(r) : "f"(lo), "f"(hi));
    return r;
}
__device__ __forceinline__ float2 unpack2(ull v) {
    float lo, hi;
    asm("mov.b64 {%0, %1}, %2;" : "=f"(lo), "=f"(hi) : "l"(v));
    return make_float2(lo, hi);
}

// ---------------------------------------------------------------------------
// K_A: fused setup kernel. Block ranges:
//   [0, 512)        filter net (8 filters per block)
//   [512, 708)      segment offsets (binary search over sorted seg_ids)
//   [708, 964)      histogram of idxe (smem-privatized -> atomic merge)
// All three are independent; fusing lets them overlap on the chip.
// ---------------------------------------------------------------------------
#define FPB 8
#define FILTER_BLOCKS (N_FILTERS / FPB)          // 512
#define SEG_BLOCKS    196                        // 196*256 = 50176 >= 50001
#define HISTB         256
#define SETUP_GRID    (FILTER_BLOCKS + SEG_BLOCKS + HISTB)

__global__ void setup_kernel(const float* __restrict__ ef,
                             const float* __restrict__ W1,
                             const float* __restrict__ b1,
                             const float* __restrict__ W2,
                             const float* __restrict__ b2,
                             const int*   __restrict__ seg_ids,
                             const int*   __restrict__ idxe,
                             int nE, int nNodes) {
    __shared__ __align__(16) union {
        struct { float s_ef[FPB * EDGE_FEAT]; float s_h[HIDDEN * FPB]; } fn;  // 5 KB
        int hist[N_FILTERS];                                                  // 16 KB
    } sm;

    const int b = blockIdx.x;
    const int t = threadIdx.x;   // 0..255

    if (b < FILTER_BLOCKS) {
        // ---------------- filter net ----------------
        const int f0 = b * FPB;
        if (t < FPB * EDGE_FEAT)
            sm.fn.s_ef[t] = ef[f0 * EDGE_FEAT + t];
        __syncthreads();

        // Phase 1: h[f][k] = relu(b1[k] + sum_j ef[f][j]*W1[j][k])
        {
            const int k  = t & 127;
            const int fg = (t >> 7) * 4;          // 4 filters per thread
            float accs[4];
            const float bb = b1[k];
#pragma unroll
            for (int f = 0; f < 4; f++) accs[f] = bb;
            for (int j = 0; j < EDGE_FEAT; j++) {
                const float w1 = W1[j * HIDDEN + k];
#pragma unroll
                for (int f = 0; f < 4; f++)
                    accs[f] = fmaf(sm.fn.s_ef[(fg + f) * EDGE_FEAT + j], w1, accs[f]);
            }
#pragma unroll
            for (int f = 0; f < 4; f++)
                sm.fn.s_h[k * FPB + fg + f] = fmaxf(accs[f], 0.0f);
        }
        __syncthreads();

        // Phase 2 (packed f32x2): weights[f][m] = b2[m] + sum_k h[f][k]*W2[k][m]
        {
            const ull* __restrict__ sh8 = (const ull*)sm.fn.s_h;  // pairs over f
            ull a2[4];
            const float bb2 = b2[t];
            const ull bb2p = pack2(bb2, bb2);
#pragma unroll
            for (int j = 0; j < 4; j++) a2[j] = bb2p;
            for (int kk = 0; kk < HIDDEN; kk++) {
                const float w2 = W2[kk * 256 + t];
                const ull w2p = pack2(w2, w2);
#pragma unroll
                for (int j = 0; j < 4; j++)
                    fma2(a2[j], sh8[kk * 4 + j], w2p);
            }
#pragma unroll
            for (int j = 0; j < 4; j++) {
                float2 v = unpack2(a2[j]);
                g_weights[(f0 + 2 * j)     * 256 + t] = v.x;
                g_weights[(f0 + 2 * j + 1) * 256 + t] = v.y;
            }
        }
    } else if (b < FILTER_BLOCKS + SEG_BLOCKS) {
        // ---------------- segment offsets ----------------
        const int n = (b - FILTER_BLOCKS) * 256 + t;
        if (n > nNodes) return;
        int lo = 0, hi = nE;
        while (lo < hi) {
            int mid = (lo + hi) >> 1;
            if (__ldg(&seg_ids[mid]) < n) lo = mid + 1; else hi = mid;
        }
        g_segstart[n] = lo;
    } else {
        // ---------------- histogram ----------------
        const int hb = b - (FILTER_BLOCKS + SEG_BLOCKS);
        for (int i = t; i < N_FILTERS; i += 256) sm.hist[i] = 0;
        __syncthreads();
        const int nE4 = nE >> 2;
        const int4* __restrict__ idxe4 = (const int4*)idxe;
        for (int q = hb * 256 + t; q < nE4; q += HISTB * 256) {
            int4 v = __ldg(&idxe4[q]);
            atomicAdd(&sm.hist[v.x], 1);
            atomicAdd(&sm.hist[v.y], 1);
            atomicAdd(&sm.hist[v.z], 1);
            atomicAdd(&sm.hist[v.w], 1);
        }
        if (hb == 0) {
            for (int e = nE4 * 4 + t; e < nE; e += 256)
                atomicAdd(&sm.hist[__ldg(&idxe[e])], 1);
        }
        __syncthreads();
        for (int i = t; i < N_FILTERS; i += 256) {
            int c = sm.hist[i];
            if (c) atomicAdd(&g_hist[i], c);   // g_hist zeroed by previous scan_kernel
        }
    }
}

// ---------------------------------------------------------------------------
// K_scan: exclusive scan of 4096 counts (shfl-based), then self-clean g_hist
// so the next graph replay sees zeros. 1 block, 1024 threads.
// ---------------------------------------------------------------------------
__global__ void scan_kernel() {
    __shared__ int warp_part[32];
    const int t    = threadIdx.x;
    const int lane = t & 31;
    const int wid  = t >> 5;
    const int base = t * 4;

    int4 c = *(int4*)&g_hist[base];
    const int sum = c.x + c.y + c.z + c.w;

    // inclusive warp scan of sum
    int v = sum;
#pragma unroll
    for (int off = 1; off < 32; off <<= 1) {
        int u = __shfl_up_sync(0xffffffffu, v, off);
        if (lane >= off) v += u;
    }
    if (lane == 31) warp_part[wid] = v;
    __syncthreads();
    if (wid == 0) {
        int w = warp_part[lane];
        int wi = w;
#pragma unroll
        for (int off = 1; off < 32; off <<= 1) {
            int u = __shfl_up_sync(0xffffffffu, wi, off);
            if (lane >= off) wi += u;
        }
        warp_part[lane] = wi - w;    // exclusive prefix of warp sums
    }
    __syncthreads();

    const int excl = (v - sum) + warp_part[wid];
    g_offs[base]     = excl;
    g_offs[base + 1] = excl + c.x;
    g_offs[base + 2] = excl + c.x + c.y;
    g_offs[base + 3] = excl + c.x + c.y + c.z;
    g_cursor[base]     = excl;
    g_cursor[base + 1] = excl + c.x;
    g_cursor[base + 2] = excl + c.x + c.y;
    g_cursor[base + 3] = excl + c.x + c.y + c.z;
    if (t == 1023) g_offs[N_FILTERS] = excl + sum;

    // self-clean for the next invocation (each thread owns its 4 bins)
    *(int4*)&g_hist[base] = make_int4(0, 0, 0, 0);
}

// ---------------------------------------------------------------------------
// K_scatter: edges -> filter-sorted order, 4 edges per thread.
// ---------------------------------------------------------------------------
__global__ void scatter_kernel(const int* __restrict__ idxn,
                               const int* __restrict__ idxe, int nE) {
    const int nE4 = nE >> 2;
    const int4* __restrict__ idxe4 = (const int4*)idxe;
    const int4* __restrict__ idxn4 = (const int4*)idxn;
    for (int q = blockIdx.x * blockDim.x + threadIdx.x; q < nE4;
         q += gridDim.x * blockDim.x) {
        int4 f = __ldg(&idxe4[q]);
        int4 n = __ldg(&idxn4[q]);
        int e = q * 4;
        g_sorted[atomicAdd(&g_cursor[f.x], 1)] = make_int2(e,     n.x);
        g_sorted[atomicAdd(&g_cursor[f.y], 1)] = make_int2(e + 1, n.y);
        g_sorted[atomicAdd(&g_cursor[f.z], 1)] = make_int2(e + 2, n.z);
        g_sorted[atomicAdd(&g_cursor[f.w], 1)] = make_int2(e + 3, n.w);
    }
    if (blockIdx.x == 0) {
        for (int e = nE4 * 4 + threadIdx.x; e < nE; e += blockDim.x) {
            int f = __ldg(&idxe[e]);
            g_sorted[atomicAdd(&g_cursor[f], 1)] = make_int2(e, __ldg(&idxn[e]));
        }
    }
}

// ---------------------------------------------------------------------------
// K_product: per-filter products -> fp16, packed f32x2 FMA.
// One block per filter; weight matrix broadcast from smem.
// ---------------------------------------------------------------------------
#define PT 128
__global__ void product_kernel(const float* __restrict__ input) {
    const int f = blockIdx.x;
    __shared__ __align__(16) float ws[256];
    const int t = threadIdx.x;
    ws[t]       = g_weights[f * 256 + t];
    ws[t + 128] = g_weights[f * 256 + 128 + t];
    const int beg = g_offs[f], end = g_offs[f + 1];
    __syncthreads();

    const ull* __restrict__ w8 = (const ull*)ws;   // w pair (i, 2j..2j+1) at i*8+j

    for (int p = beg + t; p < end; p += PT) {
        int2 se = g_sorted[p];
        const int e = se.x, n = se.y;
        const float4* xp = (const float4*)(input + (size_t)n * IN_CH);
        float4 x0 = __ldg(&xp[0]), x1 = __ldg(&xp[1]);
        float4 x2 = __ldg(&xp[2]), x3 = __ldg(&xp[3]);
        float xr[16] = {x0.x, x0.y, x0.z, x0.w,  x1.x, x1.y, x1.z, x1.w,
                        x2.x, x2.y, x2.z, x2.w,  x3.x, x3.y, x3.z, x3.w};
        ull a[8];
#pragma unroll
        for (int j = 0; j < 8; j++) a[j] = 0ull;   // (0.0f, 0.0f)
#pragma unroll
        for (int i = 0; i < 16; i++) {
            const ull xx = pack2(xr[i], xr[i]);
#pragma unroll
            for (int j = 0; j < 8; j++)
                fma2(a[j], xx, w8[i * 8 + j]);
        }
        __half2 h[8];
#pragma unroll
        for (int j = 0; j < 8; j++) {
            float2 v = unpack2(a[j]);
            h[j] = __floats2half2_rn(v.x, v.y);
        }
        uint4* op = (uint4*)(g_products + (size_t)e * OUT_CH);
        op[0] = *(uint4*)&h[0];
        op[1] = *(uint4*)&h[4];
    }
}

// ---------------------------------------------------------------------------
// K_segmean: segment mean over fp16 products (sequential reads).
// One warp per node; 4 edges in flight (8 lanes/edge, half2 per lane).
// ---------------------------------------------------------------------------
#define WARPS_PER_BLOCK 8
__global__ void seg_mean_kernel(float* __restrict__ out, int nNodes) {
    const int warp_id = blockIdx.x * WARPS_PER_BLOCK + (threadIdx.x >> 5);
    if (warp_id >= nNodes) return;

    const int lane = threadIdx.x & 31;
    const int g = lane >> 3;      // edge slot 0..3
    const int c = lane & 7;       // half2 index -> channels 2c, 2c+1

    const int beg = g_segstart[warp_id];
    const int end = g_segstart[warp_id + 1];
    const int deg = end - beg;

    const __half2* __restrict__ prod2 = (const __half2*)g_products;

    float ax = 0.0f, ay = 0.0f;
    for (int e = beg + g; e < end; e += 4) {
        float2 v = __half22float2(__ldg(&prod2[(size_t)e * 8 + c]));
        ax += v.x; ay += v.y;
    }

    ax += __shfl_xor_sync(0xffffffffu, ax, 8);
    ay += __shfl_xor_sync(0xffffffffu, ay, 8);
    ax += __shfl_xor_sync(0xffffffffu, ax, 16);
    ay += __shfl_xor_sync(0xffffffffu, ay, 16);

    if (lane < 8) {
        float inv = (deg > 0) ? (1.0f / (float)deg) : 0.0f;
        *(float2*)(out + (size_t)warp_id * OUT_CH + 2 * c) =
            make_float2(ax * inv, ay * inv);
    }
}

// ---------------------------------------------------------------------------
// Launch.  Inputs: input, idxn, idxe, seg_ids, edgefeats, W1, b1, W2, b2
// ---------------------------------------------------------------------------
extern "C" void kernel_launch(void* const* d_in, const int* in_sizes, int n_in,
                              void* d_out, int out_size) {
    const float* input = (const float*)d_in[0];
    const int*   idxn  = (const int*)  d_in[1];
    const int*   idxe  = (const int*)  d_in[2];
    const int*   segs  = (const int*)  d_in[3];
    const float* ef    = (const float*)d_in[4];
    const float* W1    = (const float*)d_in[5];
    const float* b1    = (const float*)d_in[6];
    const float* W2    = (const float*)d_in[7];
    const float* b2    = (const float*)d_in[8];
    float* out = (float*)d_out;

    const int nNodes = in_sizes[0] / IN_CH;
    const int nEdges = in_sizes[1];

    setup_kernel<<<SETUP_GRID, 256>>>(ef, W1, b1, W2, b2, segs, idxe, nEdges, nNodes);
    scan_kernel<<<1, 1024>>>();
    scatter_kernel<<<1024, 256>>>(idxn, idxe, nEdges);
    product_kernel<<<N_FILTERS, PT>>>(input);

    {
        int blocks = (nNodes + WARPS_PER_BLOCK - 1) / WARPS_PER_BLOCK;
        seg_mean_kernel<<<blocks, WARPS_PER_BLOCK * 32>>>(out, nNodes);
    }
}

// round 5
// speedup vs baseline: 1.3506x; 1.0011x over previous
#include <cuda_runtime.h>
#include <cuda_fp16.h>

#define N_NODES   50000
#define N_FILTERS 4096
#define EDGE_FEAT 32
#define HIDDEN    128
#define IN_CH     16
#define OUT_CH    16
#define MAX_EDGES 1600000

// ---- scratch (static device globals; zero-initialized at module load) ----
__device__ float  g_weights[N_FILTERS * IN_CH * OUT_CH];   // 4 MB
__device__ int    g_segstart[N_NODES + 1];
__device__ int    g_hist[N_FILTERS];                       // self-cleaned by scan_kernel
__device__ int    g_offs[N_FILTERS + 1];
__device__ int    g_cursor[N_FILTERS];
__device__ int2   g_sorted[MAX_EDGES];                     // {orig edge id, src node}
__device__ __half g_products[(size_t)MAX_EDGES * OUT_CH];  // 51 MB (fp16)

typedef unsigned long long ull;

// packed f32x2 FMA: d = a*b + d  (two fp32 lanes per instruction)
__device__ __forceinline__ void fma2(ull& d, ull a, ull b) {
    asm("fma.rn.f32x2 %0, %1, %2, %0;" : "+l"(d) : "l"(a), "l"(b));
}
__device__ __forceinline__ ull pack2(float lo, float hi) {
    ull r;
    asm("mov.b64 %0, {%1, %2};" : "=l"(r) : "f"(lo), "f"(hi));
    return r;
}
__device__ __forceinline__ float2 unpack2(ull v) {
    float lo, hi;
    asm("mov.b64 {%0, %1}, %2;" : "=f"(lo), "=f"(hi) : "l"(v));
    return make_float2(lo, hi);
}

// ---------------------------------------------------------------------------
// K_A: fused setup kernel. Block ranges:
//   [0, 512)        filter net (8 filters per block)
//   [512, 708)      segment offsets (binary search over sorted seg_ids)
//   [708, 964)      histogram of idxe (smem-privatized -> atomic merge)
// ---------------------------------------------------------------------------
#define FPB 8
#define FILTER_BLOCKS (N_FILTERS / FPB)          // 512
#define SEG_BLOCKS    196                        // 196*256 = 50176 >= 50001
#define HISTB         256
#define SETUP_GRID    (FILTER_BLOCKS + SEG_BLOCKS + HISTB)

__global__ void setup_kernel(const float* __restrict__ ef,
                             const float* __restrict__ W1,
                             const float* __restrict__ b1,
                             const float* __restrict__ W2,
                             const float* __restrict__ b2,
                             const int*   __restrict__ seg_ids,
                             const int*   __restrict__ idxe,
                             int nE, int nNodes) {
    __shared__ __align__(16) union {
        struct { float s_ef[FPB * EDGE_FEAT]; float s_h[HIDDEN * FPB]; } fn;  // 5 KB
        int hist[N_FILTERS];                                                  // 16 KB
    } sm;

    const int b = blockIdx.x;
    const int t = threadIdx.x;   // 0..255

    if (b < FILTER_BLOCKS) {
        // ---------------- filter net ----------------
        const int f0 = b * FPB;
        if (t < FPB * EDGE_FEAT)
            sm.fn.s_ef[t] = ef[f0 * EDGE_FEAT + t];
        __syncthreads();

        {
            const int k  = t & 127;
            const int fg = (t >> 7) * 4;          // 4 filters per thread
            float accs[4];
            const float bb = b1[k];
#pragma unroll
            for (int f = 0; f < 4; f++) accs[f] = bb;
            for (int j = 0; j < EDGE_FEAT; j++) {
                const float w1 = W1[j * HIDDEN + k];
#pragma unroll
                for (int f = 0; f < 4; f++)
                    accs[f] = fmaf(sm.fn.s_ef[(fg + f) * EDGE_FEAT + j], w1, accs[f]);
            }
#pragma unroll
            for (int f = 0; f < 4; f++)
                sm.fn.s_h[k * FPB + fg + f] = fmaxf(accs[f], 0.0f);
        }
        __syncthreads();

        {
            const ull* __restrict__ sh8 = (const ull*)sm.fn.s_h;  // pairs over f
            ull a2[4];
            const float bb2 = b2[t];
            const ull bb2p = pack2(bb2, bb2);
#pragma unroll
            for (int j = 0; j < 4; j++) a2[j] = bb2p;
            for (int kk = 0; kk < HIDDEN; kk++) {
                const float w2 = W2[kk * 256 + t];
                const ull w2p = pack2(w2, w2);
#pragma unroll
                for (int j = 0; j < 4; j++)
                    fma2(a2[j], sh8[kk * 4 + j], w2p);
            }
#pragma unroll
            for (int j = 0; j < 4; j++) {
                float2 v = unpack2(a2[j]);
                g_weights[(f0 + 2 * j)     * 256 + t] = v.x;
                g_weights[(f0 + 2 * j + 1) * 256 + t] = v.y;
            }
        }
    } else if (b < FILTER_BLOCKS + SEG_BLOCKS) {
        // ---------------- segment offsets ----------------
        const int n = (b - FILTER_BLOCKS) * 256 + t;
        if (n > nNodes) return;
        int lo = 0, hi = nE;
        while (lo < hi) {
            int mid = (lo + hi) >> 1;
            if (__ldg(&seg_ids[mid]) < n) lo = mid + 1; else hi = mid;
        }
        g_segstart[n] = lo;
    } else {
        // ---------------- histogram ----------------
        const int hb = b - (FILTER_BLOCKS + SEG_BLOCKS);
        for (int i = t; i < N_FILTERS; i += 256) sm.hist[i] = 0;
        __syncthreads();
        const int nE4 = nE >> 2;
        const int4* __restrict__ idxe4 = (const int4*)idxe;
        for (int q = hb * 256 + t; q < nE4; q += HISTB * 256) {
            int4 v = __ldg(&idxe4[q]);
            atomicAdd(&sm.hist[v.x], 1);
            atomicAdd(&sm.hist[v.y], 1);
            atomicAdd(&sm.hist[v.z], 1);
            atomicAdd(&sm.hist[v.w], 1);
        }
        if (hb == 0) {
            for (int e = nE4 * 4 + t; e < nE; e += 256)
                atomicAdd(&sm.hist[__ldg(&idxe[e])], 1);
        }
        __syncthreads();
        for (int i = t; i < N_FILTERS; i += 256) {
            int c = sm.hist[i];
            if (c) atomicAdd(&g_hist[i], c);   // g_hist zeroed by previous scan_kernel
        }
    }
}

// ---------------------------------------------------------------------------
// K_scan: exclusive scan of 4096 counts (shfl-based), then self-clean g_hist.
// ---------------------------------------------------------------------------
__global__ void scan_kernel() {
    __shared__ int warp_part[32];
    const int t    = threadIdx.x;
    const int lane = t & 31;
    const int wid  = t >> 5;
    const int base = t * 4;

    int4 c = *(int4*)&g_hist[base];
    const int sum = c.x + c.y + c.z + c.w;

    int v = sum;
#pragma unroll
    for (int off = 1; off < 32; off <<= 1) {
        int u = __shfl_up_sync(0xffffffffu, v, off);
        if (lane >= off) v += u;
    }
    if (lane == 31) warp_part[wid] = v;
    __syncthreads();
    if (wid == 0) {
        int w = warp_part[lane];
        int wi = w;
#pragma unroll
        for (int off = 1; off < 32; off <<= 1) {
            int u = __shfl_up_sync(0xffffffffu, wi, off);
            if (lane >= off) wi += u;
        }
        warp_part[lane] = wi - w;
    }
    __syncthreads();

    const int excl = (v - sum) + warp_part[wid];
    g_offs[base]     = excl;
    g_offs[base + 1] = excl + c.x;
    g_offs[base + 2] = excl + c.x + c.y;
    g_offs[base + 3] = excl + c.x + c.y + c.z;
    g_cursor[base]     = excl;
    g_cursor[base + 1] = excl + c.x;
    g_cursor[base + 2] = excl + c.x + c.y;
    g_cursor[base + 3] = excl + c.x + c.y + c.z;
    if (t == 1023) g_offs[N_FILTERS] = excl + sum;

    *(int4*)&g_hist[base] = make_int4(0, 0, 0, 0);
}

// ---------------------------------------------------------------------------
// K_scatter: edges -> filter-sorted order, 4 edges per thread.
// ---------------------------------------------------------------------------
__global__ void scatter_kernel(const int* __restrict__ idxn,
                               const int* __restrict__ idxe, int nE) {
    const int nE4 = nE >> 2;
    const int4* __restrict__ idxe4 = (const int4*)idxe;
    const int4* __restrict__ idxn4 = (const int4*)idxn;
    for (int q = blockIdx.x * blockDim.x + threadIdx.x; q < nE4;
         q += gridDim.x * blockDim.x) {
        int4 f = __ldg(&idxe4[q]);
        int4 n = __ldg(&idxn4[q]);
        int e = q * 4;
        g_sorted[atomicAdd(&g_cursor[f.x], 1)] = make_int2(e,     n.x);
        g_sorted[atomicAdd(&g_cursor[f.y], 1)] = make_int2(e + 1, n.y);
        g_sorted[atomicAdd(&g_cursor[f.z], 1)] = make_int2(e + 2, n.z);
        g_sorted[atomicAdd(&g_cursor[f.w], 1)] = make_int2(e + 3, n.w);
    }
    if (blockIdx.x == 0) {
        for (int e = nE4 * 4 + threadIdx.x; e < nE; e += blockDim.x) {
            int f = __ldg(&idxe[e]);
            g_sorted[atomicAdd(&g_cursor[f], 1)] = make_int2(e, __ldg(&idxn[e]));
        }
    }
}

// ---------------------------------------------------------------------------
// K_product: per-filter products -> fp16, packed f32x2 FMA.
// One block per filter; TWO edges per thread so each LDS.128 weight load
// feeds FMAs for two edges (weight-LDS per edge cut 4x vs LDS.64/1-edge).
// ---------------------------------------------------------------------------
#define PT 128
__global__ void __launch_bounds__(PT) product_kernel(const float* __restrict__ input) {
    const int f = blockIdx.x;
    __shared__ __align__(16) float ws[256];
    const int t = threadIdx.x;
    ws[t]       = g_weights[f * 256 + t];
    ws[t + 128] = g_weights[f * 256 + 128 + t];
    const int beg = g_offs[f], end = g_offs[f + 1];
    __syncthreads();

    const ulonglong2* __restrict__ w16 = (const ulonglong2*)ws;  // [i*4+jj]

    for (int p = beg + t; p < end; p += 2 * PT) {
        const int p2 = p + PT;
        const bool has2 = (p2 < end);

        int2 se1 = g_sorted[p];
        int2 se2 = has2 ? g_sorted[p2] : se1;

        const float4* xp1 = (const float4*)(input + (size_t)se1.y * IN_CH);
        const float4* xp2 = (const float4*)(input + (size_t)se2.y * IN_CH);
        float4 xa0 = __ldg(&xp1[0]), xa1 = __ldg(&xp1[1]);
        float4 xa2 = __ldg(&xp1[2]), xa3 = __ldg(&xp1[3]);
        float4 xb0 = __ldg(&xp2[0]), xb1 = __ldg(&xp2[1]);
        float4 xb2 = __ldg(&xp2[2]), xb3 = __ldg(&xp2[3]);
        float x1[16] = {xa0.x, xa0.y, xa0.z, xa0.w,  xa1.x, xa1.y, xa1.z, xa1.w,
                        xa2.x, xa2.y, xa2.z, xa2.w,  xa3.x, xa3.y, xa3.z, xa3.w};
        float x2[16] = {xb0.x, xb0.y, xb0.z, xb0.w,  xb1.x, xb1.y, xb1.z, xb1.w,
                        xb2.x, xb2.y, xb2.z, xb2.w,  xb3.x, xb3.y, xb3.z, xb3.w};

        ull a1[8], a2[8];
#pragma unroll
        for (int j = 0; j < 8; j++) { a1[j] = 0ull; a2[j] = 0ull; }

#pragma unroll
        for (int i = 0; i < 16; i++) {
            const ull xx1 = pack2(x1[i], x1[i]);
            const ull xx2 = pack2(x2[i], x2[i]);
#pragma unroll
            for (int jj = 0; jj < 4; jj++) {
                const ulonglong2 w = w16[i * 4 + jj];   // LDS.128 broadcast
                fma2(a1[2 * jj],     xx1, w.x);
                fma2(a1[2 * jj + 1], xx1, w.y);
                fma2(a2[2 * jj],     xx2, w.x);
                fma2(a2[2 * jj + 1], xx2, w.y);
            }
        }

        __half2 h1[8], h2[8];
#pragma unroll
        for (int j = 0; j < 8; j++) {
            float2 v1 = unpack2(a1[j]);
            float2 v2 = unpack2(a2[j]);
            h1[j] = __floats2half2_rn(v1.x, v1.y);
            h2[j] = __floats2half2_rn(v2.x, v2.y);
        }
        uint4* op1 = (uint4*)(g_products + (size_t)se1.x * OUT_CH);
        op1[0] = *(uint4*)&h1[0];
        op1[1] = *(uint4*)&h1[4];
        if (has2) {
            uint4* op2 = (uint4*)(g_products + (size_t)se2.x * OUT_CH);
            op2[0] = *(uint4*)&h2[0];
            op2[1] = *(uint4*)&h2[4];
        }
    }
}

// ---------------------------------------------------------------------------
// K_segmean: segment mean over fp16 products (sequential reads).
// One warp per node; 4 edges in flight (8 lanes/edge, half2 per lane).
// ---------------------------------------------------------------------------
#define WARPS_PER_BLOCK 8
__global__ void seg_mean_kernel(float* __restrict__ out, int nNodes) {
    const int warp_id = blockIdx.x * WARPS_PER_BLOCK + (threadIdx.x >> 5);
    if (warp_id >= nNodes) return;

    const int lane = threadIdx.x & 31;
    const int g = lane >> 3;      // edge slot 0..3
    const int c = lane & 7;       // half2 index -> channels 2c, 2c+1

    const int beg = g_segstart[warp_id];
    const int end = g_segstart[warp_id + 1];
    const int deg = end - beg;

    const __half2* __restrict__ prod2 = (const __half2*)g_products;

    float ax = 0.0f, ay = 0.0f;
    for (int e = beg + g; e < end; e += 4) {
        float2 v = __half22float2(__ldg(&prod2[(size_t)e * 8 + c]));
        ax += v.x; ay += v.y;
    }

    ax += __shfl_xor_sync(0xffffffffu, ax, 8);
    ay += __shfl_xor_sync(0xffffffffu, ay, 8);
    ax += __shfl_xor_sync(0xffffffffu, ax, 16);
    ay += __shfl_xor_sync(0xffffffffu, ay, 16);

    if (lane < 8) {
        float inv = (deg > 0) ? (1.0f / (float)deg) : 0.0f;
        *(float2*)(out + (size_t)warp_id * OUT_CH + 2 * c) =
            make_float2(ax * inv, ay * inv);
    }
}

// ---------------------------------------------------------------------------
// Launch.  Inputs: input, idxn, idxe, seg_ids, edgefeats, W1, b1, W2, b2
// ---------------------------------------------------------------------------
extern "C" void kernel_launch(void* const* d_in, const int* in_sizes, int n_in,
                              void* d_out, int out_size) {
    const float* input = (const float*)d_in[0];
    const int*   idxn  = (const int*)  d_in[1];
    const int*   idxe  = (const int*)  d_in[2];
    const int*   segs  = (const int*)  d_in[3];
    const float* ef    = (const float*)d_in[4];
    const float* W1    = (const float*)d_in[5];
    const float* b1    = (const float*)d_in[6];
    const float* W2    = (const float*)d_in[7];
    const float* b2    = (const float*)d_in[8];
    float* out = (float*)d_out;

    const int nNodes = in_sizes[0] / IN_CH;
    const int nEdges = in_sizes[1];

    setup_kernel<<<SETUP_GRID, 256>>>(ef, W1, b1, W2, b2, segs, idxe, nEdges, nNodes);
    scan_kernel<<<1, 1024>>>();
    scatter_kernel<<<1024, 256>>>(idxn, idxe, nEdges);
    product_kernel<<<N_FILTERS, PT>>>(input);

    {
        int blocks = (nNodes + WARPS_PER_BLOCK - 1) / WARPS_PER_BLOCK;
        seg_mean_kernel<<<blocks, WARPS_PER_BLOCK * 32>>>(out, nNodes);
    }
}

// round 6
// speedup vs baseline: 1.5279x; 1.1313x over previous
#include <cuda_runtime.h>
#include <cuda_fp16.h>

#define N_NODES   50000
#define N_FILTERS 4096
#define EDGE_FEAT 32
#define HIDDEN    128
#define IN_CH     16
#define OUT_CH    16
#define MAX_EDGES 1600000

// ---- scratch (static device globals; zero-initialized at module load) ----
__device__ float  g_weights[N_FILTERS * IN_CH * OUT_CH];   // 4 MB
__device__ int    g_segstart[N_NODES + 1];
__device__ int    g_hist[N_FILTERS];                       // self-cleaned by scan_kernel
__device__ int    g_offs[N_FILTERS + 1];
__device__ int    g_cursor[N_FILTERS];
__device__ int    g_snode[MAX_EDGES];                      // src node at sorted pos
__device__ int    g_rank[MAX_EDGES];                       // orig edge -> sorted pos
__device__ __half g_xh[N_NODES * IN_CH];                   // fp16 copy of input (1.6 MB)
__device__ __half g_prod[(size_t)MAX_EDGES * OUT_CH];      // products at SORTED pos (51 MB)

typedef unsigned long long ull;

// packed f32x2 FMA: d = a*b + d  (two fp32 lanes per instruction)
__device__ __forceinline__ void fma2(ull& d, ull a, ull b) {
    asm("fma.rn.f32x2 %0, %1, %2, %0;" : "+l"(d) : "l"(a), "l"(b));
}
__device__ __forceinline__ ull pack2(float lo, float hi) {
    ull r;
    asm("mov.b64 %0, {%1, %2};" : "=l"(r) : "f"(lo), "f"(hi));
    return r;
}
__device__ __forceinline__ float2 unpack2(ull v) {
    float lo, hi;
    asm("mov.b64 {%0, %1}, %2;" : "=f"(lo), "=f"(hi) : "l"(v));
    return make_float2(lo, hi);
}

// ---------------------------------------------------------------------------
// K_A: fused setup kernel. Block ranges (all independent, overlap on chip):
//   [0, 512)            filter net (8 filters per block)
//   [512, 708)          segment offsets (binary search over sorted seg_ids)
//   [708, 964)          histogram of idxe (smem-privatized -> atomic merge)
//   [964, 1355)         input fp32 -> fp16 conversion (g_xh)
// ---------------------------------------------------------------------------
#define FPB 8
#define FILTER_BLOCKS (N_FILTERS / FPB)          // 512
#define SEG_BLOCKS    196                        // 196*256 = 50176 >= 50001
#define HISTB         256
#define CVT_BLOCKS    391                        // 391*256*8 >= 800000
#define SETUP_GRID    (FILTER_BLOCKS + SEG_BLOCKS + HISTB + CVT_BLOCKS)

__global__ void setup_kernel(const float* __restrict__ ef,
                             const float* __restrict__ W1,
                             const float* __restrict__ b1,
                             const float* __restrict__ W2,
                             const float* __restrict__ b2,
                             const int*   __restrict__ seg_ids,
                             const int*   __restrict__ idxe,
                             const float* __restrict__ input,
                             int nE, int nNodes) {
    __shared__ __align__(16) union {
        struct { float s_ef[FPB * EDGE_FEAT]; float s_h[HIDDEN * FPB]; } fn;  // 5 KB
        int hist[N_FILTERS];                                                  // 16 KB
    } sm;

    const int b = blockIdx.x;
    const int t = threadIdx.x;   // 0..255

    if (b < FILTER_BLOCKS) {
        // ---------------- filter net ----------------
        const int f0 = b * FPB;
        if (t < FPB * EDGE_FEAT)
            sm.fn.s_ef[t] = ef[f0 * EDGE_FEAT + t];
        __syncthreads();

        {
            const int k  = t & 127;
            const int fg = (t >> 7) * 4;          // 4 filters per thread
            float accs[4];
            const float bb = b1[k];
#pragma unroll
            for (int f = 0; f < 4; f++) accs[f] = bb;
            for (int j = 0; j < EDGE_FEAT; j++) {
                const float w1 = W1[j * HIDDEN + k];
#pragma unroll
                for (int f = 0; f < 4; f++)
                    accs[f] = fmaf(sm.fn.s_ef[(fg + f) * EDGE_FEAT + j], w1, accs[f]);
            }
#pragma unroll
            for (int f = 0; f < 4; f++)
                sm.fn.s_h[k * FPB + fg + f] = fmaxf(accs[f], 0.0f);
        }
        __syncthreads();

        {
            const ull* __restrict__ sh8 = (const ull*)sm.fn.s_h;  // pairs over f
            ull a2[4];
            const float bb2 = b2[t];
            const ull bb2p = pack2(bb2, bb2);
#pragma unroll
            for (int j = 0; j < 4; j++) a2[j] = bb2p;
            for (int kk = 0; kk < HIDDEN; kk++) {
                const float w2 = W2[kk * 256 + t];
                const ull w2p = pack2(w2, w2);
#pragma unroll
                for (int j = 0; j < 4; j++)
                    fma2(a2[j], sh8[kk * 4 + j], w2p);
            }
#pragma unroll
            for (int j = 0; j < 4; j++) {
                float2 v = unpack2(a2[j]);
                g_weights[(f0 + 2 * j)     * 256 + t] = v.x;
                g_weights[(f0 + 2 * j + 1) * 256 + t] = v.y;
            }
        }
    } else if (b < FILTER_BLOCKS + SEG_BLOCKS) {
        // ---------------- segment offsets ----------------
        const int n = (b - FILTER_BLOCKS) * 256 + t;
        if (n > nNodes) return;
        int lo = 0, hi = nE;
        while (lo < hi) {
            int mid = (lo + hi) >> 1;
            if (__ldg(&seg_ids[mid]) < n) lo = mid + 1; else hi = mid;
        }
        g_segstart[n] = lo;
    } else if (b < FILTER_BLOCKS + SEG_BLOCKS + HISTB) {
        // ---------------- histogram ----------------
        const int hb = b - (FILTER_BLOCKS + SEG_BLOCKS);
        for (int i = t; i < N_FILTERS; i += 256) sm.hist[i] = 0;
        __syncthreads();
        const int nE4 = nE >> 2;
        const int4* __restrict__ idxe4 = (const int4*)idxe;
        for (int q = hb * 256 + t; q < nE4; q += HISTB * 256) {
            int4 v = __ldg(&idxe4[q]);
            atomicAdd(&sm.hist[v.x], 1);
            atomicAdd(&sm.hist[v.y], 1);
            atomicAdd(&sm.hist[v.z], 1);
            atomicAdd(&sm.hist[v.w], 1);
        }
        if (hb == 0) {
            for (int e = nE4 * 4 + t; e < nE; e += 256)
                atomicAdd(&sm.hist[__ldg(&idxe[e])], 1);
        }
        __syncthreads();
        for (int i = t; i < N_FILTERS; i += 256) {
            int c = sm.hist[i];
            if (c) atomicAdd(&g_hist[i], c);   // g_hist zeroed by previous scan_kernel
        }
    } else {
        // ---------------- fp32 -> fp16 input conversion ----------------
        const int cb = b - (FILTER_BLOCKS + SEG_BLOCKS + HISTB);
        const int base = (cb * 256 + t) * 8;
        if (base < N_NODES * IN_CH) {
            float4 v0 = __ldg((const float4*)(input + base));
            float4 v1 = __ldg((const float4*)(input + base + 4));
            __half2 h[4];
            h[0] = __floats2half2_rn(v0.x, v0.y);
            h[1] = __floats2half2_rn(v0.z, v0.w);
            h[2] = __floats2half2_rn(v1.x, v1.y);
            h[3] = __floats2half2_rn(v1.z, v1.w);
            *(uint4*)(g_xh + base) = *(uint4*)h;
        }
    }
}

// ---------------------------------------------------------------------------
// K_scan: exclusive scan of 4096 counts (shfl-based), then self-clean g_hist.
// ---------------------------------------------------------------------------
__global__ void scan_kernel() {
    __shared__ int warp_part[32];
    const int t    = threadIdx.x;
    const int lane = t & 31;
    const int wid  = t >> 5;
    const int base = t * 4;

    int4 c = *(int4*)&g_hist[base];
    const int sum = c.x + c.y + c.z + c.w;

    int v = sum;
#pragma unroll
    for (int off = 1; off < 32; off <<= 1) {
        int u = __shfl_up_sync(0xffffffffu, v, off);
        if (lane >= off) v += u;
    }
    if (lane == 31) warp_part[wid] = v;
    __syncthreads();
    if (wid == 0) {
        int w = warp_part[lane];
        int wi = w;
#pragma unroll
        for (int off = 1; off < 32; off <<= 1) {
            int u = __shfl_up_sync(0xffffffffu, wi, off);
            if (lane >= off) wi += u;
        }
        warp_part[lane] = wi - w;
    }
    __syncthreads();

    const int excl = (v - sum) + warp_part[wid];
    g_offs[base]     = excl;
    g_offs[base + 1] = excl + c.x;
    g_offs[base + 2] = excl + c.x + c.y;
    g_offs[base + 3] = excl + c.x + c.y + c.z;
    g_cursor[base]     = excl;
    g_cursor[base + 1] = excl + c.x;
    g_cursor[base + 2] = excl + c.x + c.y;
    g_cursor[base + 3] = excl + c.x + c.y + c.z;
    if (t == 1023) g_offs[N_FILTERS] = excl + sum;

    *(int4*)&g_hist[base] = make_int4(0, 0, 0, 0);
}

// ---------------------------------------------------------------------------
// K_scatter: edges -> filter-sorted order. Writes src node at the sorted
// position (scattered 4B) and rank[e]=pos (coalesced int4).
// ---------------------------------------------------------------------------
__global__ void scatter_kernel(const int* __restrict__ idxn,
                               const int* __restrict__ idxe, int nE) {
    const int nE4 = nE >> 2;
    const int4* __restrict__ idxe4 = (const int4*)idxe;
    const int4* __restrict__ idxn4 = (const int4*)idxn;
    for (int q = blockIdx.x * blockDim.x + threadIdx.x; q < nE4;
         q += gridDim.x * blockDim.x) {
        int4 f = __ldg(&idxe4[q]);
        int4 n = __ldg(&idxn4[q]);
        int4 r;
        r.x = atomicAdd(&g_cursor[f.x], 1);
        r.y = atomicAdd(&g_cursor[f.y], 1);
        r.z = atomicAdd(&g_cursor[f.z], 1);
        r.w = atomicAdd(&g_cursor[f.w], 1);
        g_snode[r.x] = n.x;
        g_snode[r.y] = n.y;
        g_snode[r.z] = n.z;
        g_snode[r.w] = n.w;
        *(int4*)&g_rank[q * 4] = r;
    }
    if (blockIdx.x == 0) {
        for (int e = nE4 * 4 + threadIdx.x; e < nE; e += blockDim.x) {
            int f = __ldg(&idxe[e]);
            int pos = atomicAdd(&g_cursor[f], 1);
            g_snode[pos] = __ldg(&idxn[e]);
            g_rank[e] = pos;
        }
    }
}

// ---------------------------------------------------------------------------
// K_product: per-filter products -> fp16 written at SORTED position
// (coalesced stores). fp16 x gather (2 LDG.128/edge), fp32 f32x2 FMA.
// Two edges per thread so each LDS.128 weight load feeds two edges.
// ---------------------------------------------------------------------------
#define PT 128
__global__ void __launch_bounds__(PT) product_kernel() {
    const int f = blockIdx.x;
    __shared__ __align__(16) float ws[256];
    const int t = threadIdx.x;
    ws[t]       = g_weights[f * 256 + t];
    ws[t + 128] = g_weights[f * 256 + 128 + t];
    const int beg = g_offs[f], end = g_offs[f + 1];
    __syncthreads();

    const ulonglong2* __restrict__ w16 = (const ulonglong2*)ws;  // [i*4+jj]

    for (int p = beg + t; p < end; p += 2 * PT) {
        const int p2 = p + PT;
        const bool has2 = (p2 < end);

        const int n1 = __ldg(&g_snode[p]);
        const int n2 = has2 ? __ldg(&g_snode[p2]) : n1;

        const uint4* xa = (const uint4*)(g_xh + (size_t)n1 * IN_CH);
        const uint4* xb = (const uint4*)(g_xh + (size_t)n2 * IN_CH);
        __half2 ha[8], hb[8];
        *(uint4*)&ha[0] = __ldg(&xa[0]); *(uint4*)&ha[4] = __ldg(&xa[1]);
        *(uint4*)&hb[0] = __ldg(&xb[0]); *(uint4*)&hb[4] = __ldg(&xb[1]);

        float2 xf1[8], xf2[8];
#pragma unroll
        for (int k = 0; k < 8; k++) {
            xf1[k] = __half22float2(ha[k]);
            xf2[k] = __half22float2(hb[k]);
        }

        ull a1[8], a2[8];
#pragma unroll
        for (int j = 0; j < 8; j++) { a1[j] = 0ull; a2[j] = 0ull; }

#pragma unroll
        for (int k = 0; k < 8; k++) {           // i = 2k, 2k+1
            const ull x1e = pack2(xf1[k].x, xf1[k].x);
            const ull x1o = pack2(xf1[k].y, xf1[k].y);
            const ull x2e = pack2(xf2[k].x, xf2[k].x);
            const ull x2o = pack2(xf2[k].y, xf2[k].y);
#pragma unroll
            for (int jj = 0; jj < 4; jj++) {
                const ulonglong2 we = w16[(2 * k) * 4 + jj];     // LDS.128 broadcast
                fma2(a1[2 * jj],     x1e, we.x);
                fma2(a1[2 * jj + 1], x1e, we.y);
                fma2(a2[2 * jj],     x2e, we.x);
                fma2(a2[2 * jj + 1], x2e, we.y);
                const ulonglong2 wo = w16[(2 * k + 1) * 4 + jj];
                fma2(a1[2 * jj],     x1o, wo.x);
                fma2(a1[2 * jj + 1], x1o, wo.y);
                fma2(a2[2 * jj],     x2o, wo.x);
                fma2(a2[2 * jj + 1], x2o, wo.y);
            }
        }

        __half2 h1[8], h2[8];
#pragma unroll
        for (int j = 0; j < 8; j++) {
            float2 v1 = unpack2(a1[j]);
            float2 v2 = unpack2(a2[j]);
            h1[j] = __floats2half2_rn(v1.x, v1.y);
            h2[j] = __floats2half2_rn(v2.x, v2.y);
        }
        // coalesced: consecutive lanes -> consecutive sorted positions
        uint4* op1 = (uint4*)(g_prod + (size_t)p * OUT_CH);
        op1[0] = *(uint4*)&h1[0];
        op1[1] = *(uint4*)&h1[4];
        if (has2) {
            uint4* op2 = (uint4*)(g_prod + (size_t)p2 * OUT_CH);
            op2[0] = *(uint4*)&h2[0];
            op2[1] = *(uint4*)&h2[4];
        }
    }
}

// ---------------------------------------------------------------------------
// K_segmean: segment mean; gathers products via rank permutation.
// One warp per node; 4 edges in flight (8 lanes/edge, half2 per lane).
// ---------------------------------------------------------------------------
#define WARPS_PER_BLOCK 8
__global__ void seg_mean_kernel(float* __restrict__ out, int nNodes) {
    const int warp_id = blockIdx.x * WARPS_PER_BLOCK + (threadIdx.x >> 5);
    if (warp_id >= nNodes) return;

    const int lane = threadIdx.x & 31;
    const int g = lane >> 3;      // edge slot 0..3
    const int c = lane & 7;       // half2 index -> channels 2c, 2c+1

    const int beg = g_segstart[warp_id];
    const int end = g_segstart[warp_id + 1];
    const int deg = end - beg;

    const __half2* __restrict__ prod2 = (const __half2*)g_prod;

    float ax = 0.0f, ay = 0.0f;
    for (int e = beg + g; e < end; e += 4) {
        const int pos = __ldg(&g_rank[e]);          // 8 lanes same addr -> broadcast
        float2 v = __half22float2(__ldg(&prod2[(size_t)pos * 8 + c]));
        ax += v.x; ay += v.y;
    }

    ax += __shfl_xor_sync(0xffffffffu, ax, 8);
    ay += __shfl_xor_sync(0xffffffffu, ay, 8);
    ax += __shfl_xor_sync(0xffffffffu, ax, 16);
    ay += __shfl_xor_sync(0xffffffffu, ay, 16);

    if (lane < 8) {
        float inv = (deg > 0) ? (1.0f / (float)deg) : 0.0f;
        *(float2*)(out + (size_t)warp_id * OUT_CH + 2 * c) =
            make_float2(ax * inv, ay * inv);
    }
}

// ---------------------------------------------------------------------------
// Launch.  Inputs: input, idxn, idxe, seg_ids, edgefeats, W1, b1, W2, b2
// ---------------------------------------------------------------------------
extern "C" void kernel_launch(void* const* d_in, const int* in_sizes, int n_in,
                              void* d_out, int out_size) {
    const float* input = (const float*)d_in[0];
    const int*   idxn  = (const int*)  d_in[1];
    const int*   idxe  = (const int*)  d_in[2];
    const int*   segs  = (const int*)  d_in[3];
    const float* ef    = (const float*)d_in[4];
    const float* W1    = (const float*)d_in[5];
    const float* b1    = (const float*)d_in[6];
    const float* W2    = (const float*)d_in[7];
    const float* b2    = (const float*)d_in[8];
    float* out = (float*)d_out;

    const int nNodes = in_sizes[0] / IN_CH;
    const int nEdges = in_sizes[1];

    setup_kernel<<<SETUP_GRID, 256>>>(ef, W1, b1, W2, b2, segs, idxe, input,
                                      nEdges, nNodes);
    scan_kernel<<<1, 1024>>>();
    scatter_kernel<<<1024, 256>>>(idxn, idxe, nEdges);
    product_kernel<<<N_FILTERS, PT>>>();

    {
        int blocks = (nNodes + WARPS_PER_BLOCK - 1) / WARPS_PER_BLOCK;
        seg_mean_kernel<<<blocks, WARPS_PER_BLOCK * 32>>>(out, nNodes);
    }
}

// round 8
// speedup vs baseline: 1.5590x; 1.0204x over previous
#include <cuda_runtime.h>
#include <cuda_fp16.h>
#include <cstdint>

#define N_NODES   50000
#define N_FILTERS 4096
#define EDGE_FEAT 32
#define HIDDEN    128
#define IN_CH     16
#define OUT_CH    16
#define MAX_EDGES 1600000

typedef unsigned int       u32;
typedef unsigned long long ull;

// ---- scratch (static device globals; zero-initialized at module load) ----
__device__ float  g_weights[N_FILTERS * IN_CH * OUT_CH];   // 4 MB
__device__ int    g_segstart[N_NODES + 1];
__device__ int    g_hist[N_FILTERS];                       // self-cleaned by scan_kernel
__device__ int    g_offs[N_FILTERS + 1];
__device__ int    g_cursor[N_FILTERS];
__device__ int    g_snode[MAX_EDGES];                      // src node at sorted pos
__device__ int    g_rank[MAX_EDGES];                       // orig edge -> sorted pos
__device__ __half g_xh[N_NODES * IN_CH];                   // fp16 copy of input (1.6 MB)
__device__ __half g_prod[(size_t)MAX_EDGES * OUT_CH];      // products at SORTED pos (51 MB)

// packed f32x2 FMA: d = a*b + d  (two fp32 lanes per instruction)
__device__ __forceinline__ void fma2(ull& d, ull a, ull b) {
    asm("fma.rn.f32x2 %0, %1, %2, %0;" : "+l"(d) : "l"(a), "l"(b));
}
__device__ __forceinline__ ull pack2(float lo, float hi) {
    ull r;
    asm("mov.b64 %0, {%1, %2};" : "=l"(r) : "f"(lo), "f"(hi));
    return r;
}
__device__ __forceinline__ float2 unpack2(ull v) {
    float lo, hi;
    asm("mov.b64 {%0, %1}, %2;" : "=f"(lo), "=f"(hi) : "l"(v));
    return make_float2(lo, hi);
}

// ---------------------------------------------------------------------------
// K_A: fused setup kernel. Block ranges (all independent, overlap on chip):
//   [0, 512)            filter net (8 filters per block)
//   [512, 708)          segment offsets (binary search over sorted seg_ids)
//   [708, 772)          histogram of idxe (smem-privatized -> atomic merge)
//   [772, 1163)         input fp32 -> fp16 conversion (g_xh)
// ---------------------------------------------------------------------------
#define FPB 8
#define FILTER_BLOCKS (N_FILTERS / FPB)          // 512
#define SEG_BLOCKS    196                        // 196*256 = 50176 >= 50001
#define HISTB         64
#define CVT_BLOCKS    391                        // 391*256*8 >= 800000
#define SETUP_GRID    (FILTER_BLOCKS + SEG_BLOCKS + HISTB + CVT_BLOCKS)

__global__ void setup_kernel(const float* __restrict__ ef,
                             const float* __restrict__ W1,
                             const float* __restrict__ b1,
                             const float* __restrict__ W2,
                             const float* __restrict__ b2,
                             const int*   __restrict__ seg_ids,
                             const int*   __restrict__ idxe,
                             const float* __restrict__ input,
                             int nE, int nNodes) {
    __shared__ __align__(16) union {
        struct { float s_ef[FPB * EDGE_FEAT]; float s_h[HIDDEN * FPB]; } fn;  // 5 KB
        int hist[N_FILTERS];                                                  // 16 KB
    } sm;

    const int b = blockIdx.x;
    const int t = threadIdx.x;   // 0..255

    if (b < FILTER_BLOCKS) {
        // ---------------- filter net ----------------
        const int f0 = b * FPB;
        if (t < FPB * EDGE_FEAT)
            sm.fn.s_ef[t] = ef[f0 * EDGE_FEAT + t];
        __syncthreads();

        {
            const int k  = t & 127;
            const int fg = (t >> 7) * 4;          // 4 filters per thread
            float accs[4];
            const float bb = b1[k];
#pragma unroll
            for (int f = 0; f < 4; f++) accs[f] = bb;
            for (int j = 0; j < EDGE_FEAT; j++) {
                const float w1 = W1[j * HIDDEN + k];
#pragma unroll
                for (int f = 0; f < 4; f++)
                    accs[f] = fmaf(sm.fn.s_ef[(fg + f) * EDGE_FEAT + j], w1, accs[f]);
            }
#pragma unroll
            for (int f = 0; f < 4; f++)
                sm.fn.s_h[k * FPB + fg + f] = fmaxf(accs[f], 0.0f);
        }
        __syncthreads();

        {
            const ull* __restrict__ sh8 = (const ull*)sm.fn.s_h;  // pairs over f
            ull a2[4];
            const float bb2 = b2[t];
            const ull bb2p = pack2(bb2, bb2);
#pragma unroll
            for (int j = 0; j < 4; j++) a2[j] = bb2p;
            for (int kk = 0; kk < HIDDEN; kk++) {
                const float w2 = W2[kk * 256 + t];
                const ull w2p = pack2(w2, w2);
#pragma unroll
                for (int j = 0; j < 4; j++)
                    fma2(a2[j], sh8[kk * 4 + j], w2p);
            }
#pragma unroll
            for (int j = 0; j < 4; j++) {
                float2 v = unpack2(a2[j]);
                g_weights[(f0 + 2 * j)     * 256 + t] = v.x;
                g_weights[(f0 + 2 * j + 1) * 256 + t] = v.y;
            }
        }
    } else if (b < FILTER_BLOCKS + SEG_BLOCKS) {
        // ---------------- segment offsets ----------------
        const int n = (b - FILTER_BLOCKS) * 256 + t;
        if (n > nNodes) return;
        int lo = 0, hi = nE;
        while (lo < hi) {
            int mid = (lo + hi) >> 1;
            if (__ldg(&seg_ids[mid]) < n) lo = mid + 1; else hi = mid;
        }
        g_segstart[n] = lo;
    } else if (b < FILTER_BLOCKS + SEG_BLOCKS + HISTB) {
        // ---------------- histogram ----------------
        const int hb = b - (FILTER_BLOCKS + SEG_BLOCKS);
        for (int i = t; i < N_FILTERS; i += 256) sm.hist[i] = 0;
        __syncthreads();
        const int nE4 = nE >> 2;
        const int4* __restrict__ idxe4 = (const int4*)idxe;
        for (int q = hb * 256 + t; q < nE4; q += HISTB * 256) {
            int4 v = __ldg(&idxe4[q]);
            atomicAdd(&sm.hist[v.x], 1);
            atomicAdd(&sm.hist[v.y], 1);
            atomicAdd(&sm.hist[v.z], 1);
            atomicAdd(&sm.hist[v.w], 1);
        }
        if (hb == 0) {
            for (int e = nE4 * 4 + t; e < nE; e += 256)
                atomicAdd(&sm.hist[__ldg(&idxe[e])], 1);
        }
        __syncthreads();
        for (int i = t; i < N_FILTERS; i += 256) {
            int c = sm.hist[i];
            if (c) atomicAdd(&g_hist[i], c);   // g_hist zeroed by previous scan_kernel
        }
    } else {
        // ---------------- fp32 -> fp16 input conversion ----------------
        const int cb = b - (FILTER_BLOCKS + SEG_BLOCKS + HISTB);
        const int base = (cb * 256 + t) * 8;
        if (base < N_NODES * IN_CH) {
            float4 v0 = __ldg((const float4*)(input + base));
            float4 v1 = __ldg((const float4*)(input + base + 4));
            __half2 h[4];
            h[0] = __floats2half2_rn(v0.x, v0.y);
            h[1] = __floats2half2_rn(v0.z, v0.w);
            h[2] = __floats2half2_rn(v1.x, v1.y);
            h[3] = __floats2half2_rn(v1.z, v1.w);
            *(uint4*)(g_xh + base) = *(uint4*)h;
        }
    }
}

// ---------------------------------------------------------------------------
// K_scan: exclusive scan of 4096 counts (shfl-based), then self-clean g_hist.
// ---------------------------------------------------------------------------
__global__ void scan_kernel() {
    __shared__ int warp_part[32];
    const int t    = threadIdx.x;
    const int lane = t & 31;
    const int wid  = t >> 5;
    const int base = t * 4;

    int4 c = *(int4*)&g_hist[base];
    const int sum = c.x + c.y + c.z + c.w;

    int v = sum;
#pragma unroll
    for (int off = 1; off < 32; off <<= 1) {
        int u = __shfl_up_sync(0xffffffffu, v, off);
        if (lane >= off) v += u;
    }
    if (lane == 31) warp_part[wid] = v;
    __syncthreads();
    if (wid == 0) {
        int w = warp_part[lane];
        int wi = w;
#pragma unroll
        for (int off = 1; off < 32; off <<= 1) {
            int u = __shfl_up_sync(0xffffffffu, wi, off);
            if (lane >= off) wi += u;
        }
        warp_part[lane] = wi - w;
    }
    __syncthreads();

    const int excl = (v - sum) + warp_part[wid];
    g_offs[base]     = excl;
    g_offs[base + 1] = excl + c.x;
    g_offs[base + 2] = excl + c.x + c.y;
    g_offs[base + 3] = excl + c.x + c.y + c.z;
    g_cursor[base]     = excl;
    g_cursor[base + 1] = excl + c.x;
    g_cursor[base + 2] = excl + c.x + c.y;
    g_cursor[base + 3] = excl + c.x + c.y + c.z;
    if (t == 1023) g_offs[N_FILTERS] = excl + sum;

    *(int4*)&g_hist[base] = make_int4(0, 0, 0, 0);
}

// ---------------------------------------------------------------------------
// K_scatter: edges -> filter-sorted order. Writes src node at the sorted
// position (scattered 4B) and rank[e]=pos (coalesced int4).
// ---------------------------------------------------------------------------
__global__ void scatter_kernel(const int* __restrict__ idxn,
                               const int* __restrict__ idxe, int nE) {
    const int nE4 = nE >> 2;
    const int4* __restrict__ idxe4 = (const int4*)idxe;
    const int4* __restrict__ idxn4 = (const int4*)idxn;
    for (int q = blockIdx.x * blockDim.x + threadIdx.x; q < nE4;
         q += gridDim.x * blockDim.x) {
        int4 f = __ldg(&idxe4[q]);
        int4 n = __ldg(&idxn4[q]);
        int4 r;
        r.x = atomicAdd(&g_cursor[f.x], 1);
        r.y = atomicAdd(&g_cursor[f.y], 1);
        r.z = atomicAdd(&g_cursor[f.z], 1);
        r.w = atomicAdd(&g_cursor[f.w], 1);
        g_snode[r.x] = n.x;
        g_snode[r.y] = n.y;
        g_snode[r.z] = n.z;
        g_snode[r.w] = n.w;
        *(int4*)&g_rank[q * 4] = r;
    }
    if (blockIdx.x == 0) {
        for (int e = nE4 * 4 + threadIdx.x; e < nE; e += blockDim.x) {
            int f = __ldg(&idxe[e]);
            int pos = atomicAdd(&g_cursor[f], 1);
            g_snode[pos] = __ldg(&idxn[e]);
            g_rank[e] = pos;
        }
    }
}

// ---------------------------------------------------------------------------
// K_product: per-filter products -> fp16 written at SORTED position
// (coalesced stores). fp16 x gather (2 LDG.128/edge), fp32 f32x2 FMA.
// Two edges per thread; x converted fp16->fp32 on the fly inside the k-loop
// (keeps register count low -> higher occupancy on the saturated L1 pipe).
// ---------------------------------------------------------------------------
#define PT 128
__global__ void __launch_bounds__(PT) product_kernel() {
    const int f = blockIdx.x;
    __shared__ __align__(16) float ws[256];
    const int t = threadIdx.x;
    ws[t]       = g_weights[f * 256 + t];
    ws[t + 128] = g_weights[f * 256 + 128 + t];
    const int beg = g_offs[f], end = g_offs[f + 1];
    __syncthreads();

    const ulonglong2* __restrict__ w16 = (const ulonglong2*)ws;  // [i*4+jj]

    for (int p = beg + t; p < end; p += 2 * PT) {
        const int p2 = p + PT;
        const bool has2 = (p2 < end);

        const int n1 = __ldg(&g_snode[p]);
        const int n2 = has2 ? __ldg(&g_snode[p2]) : n1;

        const uint4* xa = (const uint4*)(g_xh + (size_t)n1 * IN_CH);
        const uint4* xb = (const uint4*)(g_xh + (size_t)n2 * IN_CH);
        u32 ha[8], hb[8];   // raw half2 payloads
        *(uint4*)&ha[0] = __ldg(&xa[0]); *(uint4*)&ha[4] = __ldg(&xa[1]);
        *(uint4*)&hb[0] = __ldg(&xb[0]); *(uint4*)&hb[4] = __ldg(&xb[1]);

        ull a1[8], a2[8];
#pragma unroll
        for (int j = 0; j < 8; j++) { a1[j] = 0ull; a2[j] = 0ull; }

#pragma unroll
        for (int k = 0; k < 8; k++) {           // i = 2k, 2k+1
            const float2 f1 = __half22float2(*(const __half2*)&ha[k]);
            const float2 f2 = __half22float2(*(const __half2*)&hb[k]);
            const ull x1e = pack2(f1.x, f1.x);
            const ull x1o = pack2(f1.y, f1.y);
            const ull x2e = pack2(f2.x, f2.x);
            const ull x2o = pack2(f2.y, f2.y);
#pragma unroll
            for (int jj = 0; jj < 4; jj++) {
                const ulonglong2 we = w16[(2 * k) * 4 + jj];     // LDS.128 broadcast
                fma2(a1[2 * jj],     x1e, we.x);
                fma2(a1[2 * jj + 1], x1e, we.y);
                fma2(a2[2 * jj],     x2e, we.x);
                fma2(a2[2 * jj + 1], x2e, we.y);
                const ulonglong2 wo = w16[(2 * k + 1) * 4 + jj];
                fma2(a1[2 * jj],     x1o, wo.x);
                fma2(a1[2 * jj + 1], x1o, wo.y);
                fma2(a2[2 * jj],     x2o, wo.x);
                fma2(a2[2 * jj + 1], x2o, wo.y);
            }
        }

        __half2 h1[8], h2[8];
#pragma unroll
        for (int j = 0; j < 8; j++) {
            float2 v1 = unpack2(a1[j]);
            float2 v2 = unpack2(a2[j]);
            h1[j] = __floats2half2_rn(v1.x, v1.y);
            h2[j] = __floats2half2_rn(v2.x, v2.y);
        }
        // coalesced: consecutive lanes -> consecutive sorted positions
        uint4* op1 = (uint4*)(g_prod + (size_t)p * OUT_CH);
        op1[0] = *(uint4*)&h1[0];
        op1[1] = *(uint4*)&h1[4];
        if (has2) {
            uint4* op2 = (uint4*)(g_prod + (size_t)p2 * OUT_CH);
            op2[0] = *(uint4*)&h2[0];
            op2[1] = *(uint4*)&h2[4];
        }
    }
}

// ---------------------------------------------------------------------------
// K_segmean: segment mean; gathers products via rank permutation.
// One warp per node; 8 edges in flight (4 lanes/edge, 8B = 4 channels/lane)
// for 2x the gather MLP of the previous 4-slot layout.
// ---------------------------------------------------------------------------
#define WARPS_PER_BLOCK 8
__global__ void seg_mean_kernel(float* __restrict__ out, int nNodes) {
    const int warp_id = blockIdx.x * WARPS_PER_BLOCK + (threadIdx.x >> 5);
    if (warp_id >= nNodes) return;

    const int lane = threadIdx.x & 31;
    const int g = lane >> 2;      // edge slot 0..7
    const int c = lane & 3;       // 8B chunk -> channels 4c..4c+3

    const int beg = g_segstart[warp_id];
    const int end = g_segstart[warp_id + 1];
    const int deg = end - beg;

    float a0 = 0.f, a1 = 0.f, a2 = 0.f, a3 = 0.f;
    for (int e = beg + g; e < end; e += 8) {
        const int pos = __ldg(&g_rank[e]);          // 4 lanes same addr -> broadcast
        const uint2 v = __ldg((const uint2*)(g_prod + (size_t)pos * OUT_CH) + c);
        const float2 f0 = __half22float2(*(const __half2*)&v.x);
        const float2 f1 = __half22float2(*(const __half2*)&v.y);
        a0 += f0.x; a1 += f0.y; a2 += f1.x; a3 += f1.y;
    }

#pragma unroll
    for (int mask = 4; mask <= 16; mask <<= 1) {
        a0 += __shfl_xor_sync(0xffffffffu, a0, mask);
        a1 += __shfl_xor_sync(0xffffffffu, a1, mask);
        a2 += __shfl_xor_sync(0xffffffffu, a2, mask);
        a3 += __shfl_xor_sync(0xffffffffu, a3, mask);
    }

    if (lane < 4) {
        const float inv = (deg > 0) ? (1.0f / (float)deg) : 0.0f;
        float4 r = make_float4(a0 * inv, a1 * inv, a2 * inv, a3 * inv);
        *(float4*)(out + (size_t)warp_id * OUT_CH + 4 * lane) = r;
    }
}

// ---------------------------------------------------------------------------
// Launch.  Inputs: input, idxn, idxe, seg_ids, edgefeats, W1, b1, W2, b2
// ---------------------------------------------------------------------------
extern "C" void kernel_launch(void* const* d_in, const int* in_sizes, int n_in,
                              void* d_out, int out_size) {
    const float* input = (const float*)d_in[0];
    const int*   idxn  = (const int*)  d_in[1];
    const int*   idxe  = (const int*)  d_in[2];
    const int*   segs  = (const int*)  d_in[3];
    const float* ef    = (const float*)d_in[4];
    const float* W1    = (const float*)d_in[5];
    const float* b1    = (const float*)d_in[6];
    const float* W2    = (const float*)d_in[7];
    const float* b2    = (const float*)d_in[8];
    float* out = (float*)d_out;

    const int nNodes = in_sizes[0] / IN_CH;
    const int nEdges = in_sizes[1];

    setup_kernel<<<SETUP_GRID, 256>>>(ef, W1, b1, W2, b2, segs, idxe, input,
                                      nEdges, nNodes);
    scan_kernel<<<1, 1024>>>();
    scatter_kernel<<<1024, 256>>>(idxn, idxe, nEdges);
    product_kernel<<<N_FILTERS, PT>>>();

    {
        int blocks = (nNodes + WARPS_PER_BLOCK - 1) / WARPS_PER_BLOCK;
        seg_mean_kernel<<<blocks, WARPS_PER_BLOCK * 32>>>(out, nNodes);
    }
}